// round 5
// baseline (speedup 1.0000x reference)
#include <cuda_runtime.h>
#include <cuda_bf16.h>
#include <math_constants.h>
#include <cstdint>

#define NTOK 8192
#define EDIM 768
#define E3   2304
#define HD   64
#define ATTN_SCALE 0.125f

// ---------------- scratch (device globals; allocation-free rule) -----------
__device__ float g_qkv[NTOK * E3];           // fp32 q|k|v, attention input
__device__ float g_o[NTOK * EDIM];           // attention output
__device__ __nv_bfloat16 g_xhi[NTOK * EDIM];
__device__ __nv_bfloat16 g_xlo[NTOK * EDIM];
__device__ __nv_bfloat16 g_wqhi[E3 * EDIM];
__device__ __nv_bfloat16 g_wqlo[E3 * EDIM];
__device__ __nv_bfloat16 g_wohi[EDIM * EDIM];
__device__ __nv_bfloat16 g_wolo[EDIM * EDIM];
__device__ __nv_bfloat16 g_onhi[NTOK * EDIM];
__device__ __nv_bfloat16 g_onlo[NTOK * EDIM];

// ---------------------------------------------------------------------------
// Warp-level bf16 MMA (legacy HMMA path — works on compute_103 target).
// ---------------------------------------------------------------------------
__device__ __forceinline__ void mma16816(float* c, const uint32_t* a, const uint32_t* b)
{
    asm volatile(
        "mma.sync.aligned.m16n8k16.row.col.f32.bf16.bf16.f32 "
        "{%0,%1,%2,%3}, {%4,%5,%6,%7}, {%8,%9}, {%0,%1,%2,%3};"
        : "+f"(c[0]), "+f"(c[1]), "+f"(c[2]), "+f"(c[3])
        : "r"(a[0]), "r"(a[1]), "r"(a[2]), "r"(a[3]), "r"(b[0]), "r"(b[1]));
}

// ---------------------------------------------------------------------------
// Split-bf16 tensor-core GEMM: C[8192,NTOT] = A[8192,768] @ B[NTOT,768]^T + bias
// A≈Ahi+Alo, B≈Bhi+Blo;  C = AhiBhi + AhiBlo + AloBhi  (fp32 accum).
// Block 128x128, 8 warps x (64x32), K-chunk 32, double-buffered smem.
// Smem tile: 128 rows x 40 bf16 (pad 8 -> conflict-free frag loads), 10240 B.
// Layout: stage s in {0,1}, tile t in {Ahi,Alo,Bhi,Blo}: offset (s*4+t)*10240.
// MODE 0: A=g_x*,  B=g_wq*, C=g_qkv (NTOT=2304)
// MODE 1: A=g_on*, B=g_wo*, C=Cout  (NTOT=768)
// ---------------------------------------------------------------------------
#define TILE_B 10240
#define STG_B  40960

template <int MODE>
__global__ __launch_bounds__(256) void wgemm(const float* __restrict__ bias,
                                             float* __restrict__ Cout)
{
    constexpr int NTOT = (MODE == 0) ? E3 : EDIM;
    constexpr int NC = 24;                 // 768 / 32
    extern __shared__ char smem[];

    const int tid = threadIdx.x;
    const int lane = tid & 31;
    const int wid = tid >> 5;
    const int rowBase = blockIdx.y << 7;
    const int colBase = blockIdx.x << 7;
    const int mBase = (wid & 1) * 64;      // warp row offset in tile
    const int nBase = (wid >> 1) * 32;     // warp col offset in tile

    const __nv_bfloat16* Ahi = (MODE == 0) ? g_xhi : g_onhi;
    const __nv_bfloat16* Alo = (MODE == 0) ? g_xlo : g_onlo;
    const __nv_bfloat16* Bhi = (MODE == 0) ? g_wqhi : g_wohi;
    const __nv_bfloat16* Blo = (MODE == 0) ? g_wqlo : g_wolo;
    float* C = (MODE == 0) ? g_qkv : Cout;

    // global-load assignment: thread -> (row = tid>>1, 16-elem half = tid&1)
    const int lr = tid >> 1;
    const int lh = tid & 1;
    const __nv_bfloat16* gA0 = Ahi + (size_t)(rowBase + lr) * EDIM + lh * 16;
    const __nv_bfloat16* gA1 = Alo + (size_t)(rowBase + lr) * EDIM + lh * 16;
    const __nv_bfloat16* gB0 = Bhi + (size_t)(colBase + lr) * EDIM + lh * 16;
    const __nv_bfloat16* gB1 = Blo + (size_t)(colBase + lr) * EDIM + lh * 16;
    const uint32_t soff = (uint32_t)(lr * 80 + lh * 32);   // bytes into a tile

    float acc[4][4][4];
#pragma unroll
    for (int mi = 0; mi < 4; ++mi)
#pragma unroll
        for (int ni = 0; ni < 4; ++ni)
#pragma unroll
            for (int r = 0; r < 4; ++r) acc[mi][ni][r] = 0.f;

    // preload chunk 0 into stage 0
    {
        char* st = smem;
        *(uint4*)(st + 0 * TILE_B + soff)      = *(const uint4*)(gA0);
        *(uint4*)(st + 0 * TILE_B + soff + 16) = *(const uint4*)(gA0 + 8);
        *(uint4*)(st + 1 * TILE_B + soff)      = *(const uint4*)(gA1);
        *(uint4*)(st + 1 * TILE_B + soff + 16) = *(const uint4*)(gA1 + 8);
        *(uint4*)(st + 2 * TILE_B + soff)      = *(const uint4*)(gB0);
        *(uint4*)(st + 2 * TILE_B + soff + 16) = *(const uint4*)(gB0 + 8);
        *(uint4*)(st + 3 * TILE_B + soff)      = *(const uint4*)(gB1);
        *(uint4*)(st + 3 * TILE_B + soff + 16) = *(const uint4*)(gB1 + 8);
    }
    __syncthreads();

    const int g = lane >> 2;     // group id 0..7
    const int q = lane & 3;      // quad lane

    for (int c = 0; c < NC; ++c) {
        const int stg = c & 1;

        // issue next chunk's global loads into registers
        uint4 ra[8];
        if (c + 1 < NC) {
            const int off = (c + 1) * 32;
            ra[0] = *(const uint4*)(gA0 + off); ra[1] = *(const uint4*)(gA0 + off + 8);
            ra[2] = *(const uint4*)(gA1 + off); ra[3] = *(const uint4*)(gA1 + off + 8);
            ra[4] = *(const uint4*)(gB0 + off); ra[5] = *(const uint4*)(gB0 + off + 8);
            ra[6] = *(const uint4*)(gB1 + off); ra[7] = *(const uint4*)(gB1 + off + 8);
        }

        // compute on current stage
        const char* As = smem + stg * STG_B;
        const char* Al = As + TILE_B;
        const char* Bh = As + 2 * TILE_B;
        const char* Bl = As + 3 * TILE_B;
#pragma unroll
        for (int k0 = 0; k0 < 32; k0 += 16) {
            uint32_t ahi[4][4], alo[4][4];
#pragma unroll
            for (int mi = 0; mi < 4; ++mi)
#pragma unroll
                for (int r = 0; r < 4; ++r) {
                    const int row = mBase + mi * 16 + g + 8 * (r & 1);
                    const int col = k0 + q * 2 + 8 * (r >> 1);
                    ahi[mi][r] = *(const uint32_t*)(As + row * 80 + col * 2);
                    alo[mi][r] = *(const uint32_t*)(Al + row * 80 + col * 2);
                }
            uint32_t bhi[4][2], blo[4][2];
#pragma unroll
            for (int ni = 0; ni < 4; ++ni)
#pragma unroll
                for (int r = 0; r < 2; ++r) {
                    const int nr = nBase + ni * 8 + g;
                    const int col = k0 + q * 2 + 8 * r;
                    bhi[ni][r] = *(const uint32_t*)(Bh + nr * 80 + col * 2);
                    blo[ni][r] = *(const uint32_t*)(Bl + nr * 80 + col * 2);
                }
#pragma unroll
            for (int mi = 0; mi < 4; ++mi)
#pragma unroll
                for (int ni = 0; ni < 4; ++ni) {
                    mma16816(acc[mi][ni], ahi[mi], bhi[ni]);
                    mma16816(acc[mi][ni], ahi[mi], blo[ni]);
                    mma16816(acc[mi][ni], alo[mi], bhi[ni]);
                }
        }

        // store next chunk into the other stage (safe: not being read)
        if (c + 1 < NC) {
            char* st = smem + ((c + 1) & 1) * STG_B;
            *(uint4*)(st + 0 * TILE_B + soff)      = ra[0];
            *(uint4*)(st + 0 * TILE_B + soff + 16) = ra[1];
            *(uint4*)(st + 1 * TILE_B + soff)      = ra[2];
            *(uint4*)(st + 1 * TILE_B + soff + 16) = ra[3];
            *(uint4*)(st + 2 * TILE_B + soff)      = ra[4];
            *(uint4*)(st + 2 * TILE_B + soff + 16) = ra[5];
            *(uint4*)(st + 3 * TILE_B + soff)      = ra[6];
            *(uint4*)(st + 3 * TILE_B + soff + 16) = ra[7];
        }
        __syncthreads();
    }

    // epilogue: bias add + store fp32
#pragma unroll
    for (int mi = 0; mi < 4; ++mi) {
        const int row0 = rowBase + mBase + mi * 16 + g;
#pragma unroll
        for (int ni = 0; ni < 4; ++ni) {
            const int colg = colBase + nBase + ni * 8 + q * 2;
            const float b0 = bias[colg], b1 = bias[colg + 1];
            float* c0 = C + (size_t)row0 * NTOT + colg;
            float* c1 = C + (size_t)(row0 + 8) * NTOT + colg;
            c0[0] = acc[mi][ni][0] + b0; c0[1] = acc[mi][ni][1] + b1;
            c1[0] = acc[mi][ni][2] + b0; c1[1] = acc[mi][ni][3] + b1;
        }
    }
}

// ---------------------------------------------------------------------------
// fp32 -> bf16 hi/lo split. WHICH 0: x, 1: w_qkv, 2: w_out
// ---------------------------------------------------------------------------
template <int WHICH>
__global__ void split_k(const float* __restrict__ src)
{
    __nv_bfloat16* hi = (WHICH == 0) ? g_xhi : (WHICH == 1) ? g_wqhi : g_wohi;
    __nv_bfloat16* lo = (WHICH == 0) ? g_xlo : (WHICH == 1) ? g_wqlo : g_wolo;
    const int i = blockIdx.x * blockDim.x + threadIdx.x;
    float4 v = ((const float4*)src)[i];
    float a[4] = {v.x, v.y, v.z, v.w};
    const int base = i * 4;
#pragma unroll
    for (int j = 0; j < 4; ++j) {
        __nv_bfloat16 h = __float2bfloat16_rn(a[j]);
        hi[base + j] = h;
        lo[base + j] = __float2bfloat16_rn(a[j] - __bfloat162float(h));
    }
}

// ---------------------------------------------------------------------------
// Dilated flash attention (fp32 path): 28 problems, 2048q x 2048k x 64
// ---------------------------------------------------------------------------
__global__ __launch_bounds__(256, 2) void dilated_attn()
{
    __shared__ float Qst[64][64];
    __shared__ float KPst[64][64];
    __shared__ float Vs[64][64];

    const float* __restrict__ qkv = g_qkv;

    const int p = blockIdx.y;
    int mseg, hh, grp, s, r, off;
    if (p < 16)      { grp = 0; mseg = p >> 2;        hh = p & 3;        s = 2048; r = 1; off = 0; }
    else if (p < 24) { grp = 1; mseg = (p - 16) >> 2; hh = (p - 16) & 3; s = 4096; r = 2; off = 1; }
    else             { grp = 2; mseg = 0;             hh = p - 24;       s = 8192; r = 4; off = 2; }
    const int h = grp * 4 + hh;
    const int segBase = mseg * s + off;

    const int tid = threadIdx.x;
    const int tx = tid & 15;
    const int ty = tid >> 4;
    const int lr = tid >> 2;
    const int ld = (tid & 3) << 2;

    {
        const int tok = segBase + (blockIdx.x * 64 + lr) * r;
        const float* qp = qkv + (size_t)tok * E3 + h * HD;
#pragma unroll
        for (int ii = 0; ii < 4; ++ii) {
            const int d = ld + ii * 16;
            float4 v = *(const float4*)(qp + d);
            Qst[d+0][lr] = v.x; Qst[d+1][lr] = v.y; Qst[d+2][lr] = v.z; Qst[d+3][lr] = v.w;
        }
    }

    float mreg[4], lreg[4], oacc[4][4];
#pragma unroll
    for (int i = 0; i < 4; ++i) {
        mreg[i] = -CUDART_INF_F; lreg[i] = 0.f;
#pragma unroll
        for (int j = 0; j < 4; ++j) oacc[i][j] = 0.f;
    }

    for (int kt = 0; kt < 32; ++kt) {
        __syncthreads();
        {
            const int tok = segBase + (kt * 64 + lr) * r;
            const float* kp = qkv + (size_t)tok * E3 + EDIM + h * HD;
            const float* vp = kp + EDIM;
#pragma unroll
            for (int ii = 0; ii < 4; ++ii) {
                const int d = ld + ii * 16;
                float4 kv = *(const float4*)(kp + d);
                KPst[d+0][lr] = kv.x; KPst[d+1][lr] = kv.y; KPst[d+2][lr] = kv.z; KPst[d+3][lr] = kv.w;
                *(float4*)&Vs[lr][d] = *(const float4*)(vp + d);
            }
        }
        __syncthreads();

        float sc[4][4];
#pragma unroll
        for (int i = 0; i < 4; ++i)
#pragma unroll
            for (int j = 0; j < 4; ++j) sc[i][j] = 0.f;
#pragma unroll 8
        for (int d = 0; d < 64; ++d) {
            float4 qa = *(const float4*)&Qst[d][ty * 4];
            float4 kb = *(const float4*)&KPst[d][tx * 4];
            float a[4] = {qa.x, qa.y, qa.z, qa.w};
            float b[4] = {kb.x, kb.y, kb.z, kb.w};
#pragma unroll
            for (int i = 0; i < 4; ++i)
#pragma unroll
                for (int j = 0; j < 4; ++j) sc[i][j] = fmaf(a[i], b[j], sc[i][j]);
        }
#pragma unroll
        for (int i = 0; i < 4; ++i)
#pragma unroll
            for (int j = 0; j < 4; ++j) sc[i][j] *= ATTN_SCALE;

#pragma unroll
        for (int i = 0; i < 4; ++i) {
            float tm = fmaxf(fmaxf(sc[i][0], sc[i][1]), fmaxf(sc[i][2], sc[i][3]));
#pragma unroll
            for (int w = 8; w >= 1; w >>= 1)
                tm = fmaxf(tm, __shfl_xor_sync(0xffffffffu, tm, w));
            float nm = fmaxf(mreg[i], tm);
            float corr = __expf(mreg[i] - nm);
            float rs = 0.f;
#pragma unroll
            for (int j = 0; j < 4; ++j) { sc[i][j] = __expf(sc[i][j] - nm); rs += sc[i][j]; }
#pragma unroll
            for (int w = 8; w >= 1; w >>= 1)
                rs += __shfl_xor_sync(0xffffffffu, rs, w);
            lreg[i] = lreg[i] * corr + rs;
            mreg[i] = nm;
#pragma unroll
            for (int j = 0; j < 4; ++j) oacc[i][j] *= corr;
        }

        __syncthreads();
#pragma unroll
        for (int i = 0; i < 4; ++i)
#pragma unroll
            for (int j = 0; j < 4; ++j)
                KPst[tx * 4 + j][ty * 4 + i] = sc[i][j];
        __syncthreads();

#pragma unroll 8
        for (int kk = 0; kk < 64; ++kk) {
            float4 pa = *(const float4*)&KPst[kk][ty * 4];
            float4 vb = *(const float4*)&Vs[kk][tx * 4];
            float a[4] = {pa.x, pa.y, pa.z, pa.w};
            float b[4] = {vb.x, vb.y, vb.z, vb.w};
#pragma unroll
            for (int i = 0; i < 4; ++i)
#pragma unroll
                for (int j = 0; j < 4; ++j) oacc[i][j] = fmaf(a[i], b[j], oacc[i][j]);
        }
    }

#pragma unroll
    for (int i = 0; i < 4; ++i) {
        const float inv = 1.f / lreg[i];
        const int tok = segBase + (blockIdx.x * 64 + ty * 4 + i) * r;
        *(float4*)(g_o + (size_t)tok * EDIM + h * HD + tx * 4) =
            make_float4(oacc[i][0] * inv, oacc[i][1] * inv,
                        oacc[i][2] * inv, oacc[i][3] * inv);
    }
}

// ---------------------------------------------------------------------------
// LayerNorm over 768; emits bf16 hi/lo directly for the tensor-core out-proj.
// ---------------------------------------------------------------------------
__global__ __launch_bounds__(256) void layernorm_k(
    const float* __restrict__ gamma, const float* __restrict__ beta)
{
    __shared__ float red[8];
    __shared__ float bcast;
    const int row = blockIdx.x;
    const int tid = threadIdx.x;
    const int lane = tid & 31, wid = tid >> 5;
    const float* x = g_o + (size_t)row * EDIM;
    float v0 = x[tid], v1 = x[tid + 256], v2 = x[tid + 512];

    float ssum = v0 + v1 + v2;
#pragma unroll
    for (int w = 16; w >= 1; w >>= 1) ssum += __shfl_xor_sync(0xffffffffu, ssum, w);
    if (lane == 0) red[wid] = ssum;
    __syncthreads();
    if (tid < 32) {
        float t = (tid < 8) ? red[tid] : 0.f;
#pragma unroll
        for (int w = 4; w >= 1; w >>= 1) t += __shfl_xor_sync(0xffffffffu, t, w);
        if (tid == 0) bcast = t;
    }
    __syncthreads();
    const float mu = bcast * (1.f / 768.f);
    float d0 = v0 - mu, d1 = v1 - mu, d2 = v2 - mu;
    float sq = d0 * d0 + d1 * d1 + d2 * d2;
#pragma unroll
    for (int w = 16; w >= 1; w >>= 1) sq += __shfl_xor_sync(0xffffffffu, sq, w);
    __syncthreads();
    if (lane == 0) red[wid] = sq;
    __syncthreads();
    if (tid < 32) {
        float t = (tid < 8) ? red[tid] : 0.f;
#pragma unroll
        for (int w = 4; w >= 1; w >>= 1) t += __shfl_xor_sync(0xffffffffu, t, w);
        if (tid == 0) bcast = t;
    }
    __syncthreads();
    const float rstd = rsqrtf(bcast * (1.f / 768.f) + 1e-5f);
    const size_t rb = (size_t)row * EDIM;
#pragma unroll
    for (int part = 0; part < 3; ++part) {
        const int idx = tid + part * 256;
        const float d = (part == 0) ? d0 : (part == 1) ? d1 : d2;
        const float y = d * rstd * gamma[idx] + beta[idx];
        __nv_bfloat16 h = __float2bfloat16_rn(y);
        g_onhi[rb + idx] = h;
        g_onlo[rb + idx] = __float2bfloat16_rn(y - __bfloat162float(h));
    }
}

__global__ void zero_o() {
    ((float4*)g_o)[blockIdx.x * blockDim.x + threadIdx.x] =
        make_float4(0.f, 0.f, 0.f, 0.f);
}

// ---------------------------------------------------------------------------
extern "C" void kernel_launch(void* const* d_in, const int* in_sizes, int n_in,
                              void* d_out, int out_size)
{
    const float* x      = (const float*)d_in[0];
    const float* w_qkv  = (const float*)d_in[1];
    const float* b_qkv  = (const float*)d_in[2];
    const float* w_out  = (const float*)d_in[3];
    const float* b_out  = (const float*)d_in[4];
    const float* ln_g   = (const float*)d_in[5];
    const float* ln_b   = (const float*)d_in[6];
    float* out = (float*)d_out;

    const int SMEM_GEMM = 2 * STG_B;   // 80 KB
    cudaFuncSetAttribute(wgemm<0>, cudaFuncAttributeMaxDynamicSharedMemorySize, SMEM_GEMM);
    cudaFuncSetAttribute(wgemm<1>, cudaFuncAttributeMaxDynamicSharedMemorySize, SMEM_GEMM);

    // split fp32 -> bf16 hi/lo
    split_k<0><<<(NTOK * EDIM / 4) / 256, 256>>>(x);
    split_k<1><<<(E3 * EDIM / 4) / 256, 256>>>(w_qkv);
    split_k<2><<<(EDIM * EDIM / 4) / 256, 256>>>(w_out);

    // QKV projection (tensor cores, split bf16)
    dim3 g1(E3 / 128, NTOK / 128);
    wgemm<0><<<g1, 256, SMEM_GEMM>>>(b_qkv, nullptr);

    zero_o<<<(NTOK * EDIM / 4) / 256, 256>>>();

    dim3 g2(32, 28);
    dilated_attn<<<g2, 256>>>();

    layernorm_k<<<NTOK, 256>>>(ln_g, ln_b);

    // out projection (tensor cores, split bf16)
    dim3 g3(EDIM / 128, NTOK / 128);
    wgemm<1><<<g3, 256, SMEM_GEMM>>>(b_out, out);
}

// round 9
// speedup vs baseline: 1.8435x; 1.8435x over previous
#include <cuda_runtime.h>
#include <cuda_bf16.h>
#include <math_constants.h>
#include <cstdint>

#define NTOK 8192
#define EDIM 768
#define E3   2304
#define HD   64
#define CSC  0.18033688011112042f   // 0.125 * log2(e)
#define NCROWS 57344                // 4*8192 + 4*4096 + 4*2048

__device__ float g_qkv[NTOK * E3];
__device__ float g_o[NTOK * EDIM];
__device__ __nv_bfloat16 g_xhi[NTOK * EDIM];
__device__ __nv_bfloat16 g_xlo[NTOK * EDIM];
__device__ __nv_bfloat16 g_wqhi[E3 * EDIM];
__device__ __nv_bfloat16 g_wqlo[E3 * EDIM];
__device__ __nv_bfloat16 g_wohi[EDIM * EDIM];
__device__ __nv_bfloat16 g_wolo[EDIM * EDIM];
__device__ __nv_bfloat16 g_onhi[NTOK * EDIM];
__device__ __nv_bfloat16 g_onlo[NTOK * EDIM];
__device__ __nv_bfloat16 g_qchi[NCROWS * HD];
__device__ __nv_bfloat16 g_qclo[NCROWS * HD];
__device__ __nv_bfloat16 g_kchi[NCROWS * HD];
__device__ __nv_bfloat16 g_kclo[NCROWS * HD];
__device__ __nv_bfloat16 g_vthi[NCROWS * HD];  // [head][d][tokc]
__device__ __nv_bfloat16 g_vtlo[NCROWS * HD];

__device__ __forceinline__ void mma16816(float* c, const uint32_t* a, const uint32_t* b)
{
    asm volatile(
        "mma.sync.aligned.m16n8k16.row.col.f32.bf16.bf16.f32 "
        "{%0,%1,%2,%3}, {%4,%5,%6,%7}, {%8,%9}, {%0,%1,%2,%3};"
        : "+f"(c[0]), "+f"(c[1]), "+f"(c[2]), "+f"(c[3])
        : "r"(a[0]), "r"(a[1]), "r"(a[2]), "r"(a[3]), "r"(b[0]), "r"(b[1]));
}

__device__ __forceinline__ float exp2_poly(float t)
{
    t = fmaxf(t, -125.f);
    float ft = floorf(t);
    float f = t - ft;
    float p = 1.5403530e-4f;
    p = fmaf(p, f, 1.3333558e-3f);
    p = fmaf(p, f, 9.6181291e-3f);
    p = fmaf(p, f, 5.5504109e-2f);
    p = fmaf(p, f, 2.4022651e-1f);
    p = fmaf(p, f, 6.9314718e-1f);
    p = fmaf(p, f, 1.0f);
    return __int_as_float(__float_as_int(p) + (((int)ft) << 23));
}

__device__ __forceinline__ uint32_t pack_bf16x2(float odd, float even)
{
    uint32_t d;
    asm("cvt.rn.bf16x2.f32 %0, %1, %2;" : "=r"(d) : "f"(odd), "f"(even));
    return d;
}

__device__ __forceinline__ void decode_row(int row, int& h, int& tc, int& r, int& off)
{
    if (row < 32768)      { h = row >> 13;                tc = row & 8191; r = 1; off = 0; }
    else if (row < 49152) { int u = row - 32768; h = 4 + (u >> 12); tc = u & 4095; r = 2; off = 1; }
    else                  { int u = row - 49152; h = 8 + (u >> 11); tc = u & 2047; r = 4; off = 2; }
}

// ---------------------------------------------------------------------------
// wgemm: split-bf16 HMMA GEMM, C = A @ B^T + bias
// ---------------------------------------------------------------------------
#define TILE_B 10240
#define STG_B  40960

template <int MODE>
__global__ __launch_bounds__(256) void wgemm(const float* __restrict__ bias,
                                             float* __restrict__ Cout)
{
    constexpr int NTOT = (MODE == 0) ? E3 : EDIM;
    constexpr int NC = 24;
    extern __shared__ char smem[];

    const int tid = threadIdx.x;
    const int lane = tid & 31;
    const int wid = tid >> 5;
    const int rowBase = blockIdx.y << 7;
    const int colBase = blockIdx.x << 7;
    const int mBase = (wid & 1) * 64;
    const int nBase = (wid >> 1) * 32;

    const __nv_bfloat16* Ahi = (MODE == 0) ? g_xhi : g_onhi;
    const __nv_bfloat16* Alo = (MODE == 0) ? g_xlo : g_onlo;
    const __nv_bfloat16* Bhi = (MODE == 0) ? g_wqhi : g_wohi;
    const __nv_bfloat16* Blo = (MODE == 0) ? g_wqlo : g_wolo;
    float* C = (MODE == 0) ? g_qkv : Cout;

    const int lr = tid >> 1;
    const int lh = tid & 1;
    const __nv_bfloat16* gA0 = Ahi + (size_t)(rowBase + lr) * EDIM + lh * 16;
    const __nv_bfloat16* gA1 = Alo + (size_t)(rowBase + lr) * EDIM + lh * 16;
    const __nv_bfloat16* gB0 = Bhi + (size_t)(colBase + lr) * EDIM + lh * 16;
    const __nv_bfloat16* gB1 = Blo + (size_t)(colBase + lr) * EDIM + lh * 16;
    const uint32_t soff = (uint32_t)(lr * 80 + lh * 32);

    float acc[4][4][4];
#pragma unroll
    for (int mi = 0; mi < 4; ++mi)
#pragma unroll
        for (int ni = 0; ni < 4; ++ni)
#pragma unroll
            for (int r = 0; r < 4; ++r) acc[mi][ni][r] = 0.f;

    {
        char* st = smem;
        *(uint4*)(st + 0 * TILE_B + soff)      = *(const uint4*)(gA0);
        *(uint4*)(st + 0 * TILE_B + soff + 16) = *(const uint4*)(gA0 + 8);
        *(uint4*)(st + 1 * TILE_B + soff)      = *(const uint4*)(gA1);
        *(uint4*)(st + 1 * TILE_B + soff + 16) = *(const uint4*)(gA1 + 8);
        *(uint4*)(st + 2 * TILE_B + soff)      = *(const uint4*)(gB0);
        *(uint4*)(st + 2 * TILE_B + soff + 16) = *(const uint4*)(gB0 + 8);
        *(uint4*)(st + 3 * TILE_B + soff)      = *(const uint4*)(gB1);
        *(uint4*)(st + 3 * TILE_B + soff + 16) = *(const uint4*)(gB1 + 8);
    }
    __syncthreads();

    const int g = lane >> 2;
    const int q = lane & 3;

    for (int c = 0; c < NC; ++c) {
        const int stg = c & 1;
        uint4 ra[8];
        if (c + 1 < NC) {
            const int off = (c + 1) * 32;
            ra[0] = *(const uint4*)(gA0 + off); ra[1] = *(const uint4*)(gA0 + off + 8);
            ra[2] = *(const uint4*)(gA1 + off); ra[3] = *(const uint4*)(gA1 + off + 8);
            ra[4] = *(const uint4*)(gB0 + off); ra[5] = *(const uint4*)(gB0 + off + 8);
            ra[6] = *(const uint4*)(gB1 + off); ra[7] = *(const uint4*)(gB1 + off + 8);
        }

        const char* As = smem + stg * STG_B;
        const char* Al = As + TILE_B;
        const char* Bh = As + 2 * TILE_B;
        const char* Bl = As + 3 * TILE_B;
#pragma unroll
        for (int k0 = 0; k0 < 32; k0 += 16) {
            uint32_t ahi[4][4], alo[4][4];
#pragma unroll
            for (int mi = 0; mi < 4; ++mi)
#pragma unroll
                for (int r = 0; r < 4; ++r) {
                    const int row = mBase + mi * 16 + g + 8 * (r & 1);
                    const int col = k0 + q * 2 + 8 * (r >> 1);
                    ahi[mi][r] = *(const uint32_t*)(As + row * 80 + col * 2);
                    alo[mi][r] = *(const uint32_t*)(Al + row * 80 + col * 2);
                }
            uint32_t bhi[4][2], blo[4][2];
#pragma unroll
            for (int ni = 0; ni < 4; ++ni)
#pragma unroll
                for (int r = 0; r < 2; ++r) {
                    const int nr = nBase + ni * 8 + g;
                    const int col = k0 + q * 2 + 8 * r;
                    bhi[ni][r] = *(const uint32_t*)(Bh + nr * 80 + col * 2);
                    blo[ni][r] = *(const uint32_t*)(Bl + nr * 80 + col * 2);
                }
#pragma unroll
            for (int mi = 0; mi < 4; ++mi)
#pragma unroll
                for (int ni = 0; ni < 4; ++ni) {
                    mma16816(acc[mi][ni], ahi[mi], bhi[ni]);
                    mma16816(acc[mi][ni], ahi[mi], blo[ni]);
                    mma16816(acc[mi][ni], alo[mi], bhi[ni]);
                }
        }

        if (c + 1 < NC) {
            char* st = smem + ((c + 1) & 1) * STG_B;
            *(uint4*)(st + 0 * TILE_B + soff)      = ra[0];
            *(uint4*)(st + 0 * TILE_B + soff + 16) = ra[1];
            *(uint4*)(st + 1 * TILE_B + soff)      = ra[2];
            *(uint4*)(st + 1 * TILE_B + soff + 16) = ra[3];
            *(uint4*)(st + 2 * TILE_B + soff)      = ra[4];
            *(uint4*)(st + 2 * TILE_B + soff + 16) = ra[5];
            *(uint4*)(st + 3 * TILE_B + soff)      = ra[6];
            *(uint4*)(st + 3 * TILE_B + soff + 16) = ra[7];
        }
        __syncthreads();
    }

#pragma unroll
    for (int mi = 0; mi < 4; ++mi) {
        const int row0 = rowBase + mBase + mi * 16 + g;
#pragma unroll
        for (int ni = 0; ni < 4; ++ni) {
            const int colg = colBase + nBase + ni * 8 + q * 2;
            const float b0 = bias[colg], b1 = bias[colg + 1];
            float* c0 = C + (size_t)row0 * NTOT + colg;
            float* c1 = C + (size_t)(row0 + 8) * NTOT + colg;
            c0[0] = acc[mi][ni][0] + b0; c0[1] = acc[mi][ni][1] + b1;
            c1[0] = acc[mi][ni][2] + b0; c1[1] = acc[mi][ni][3] + b1;
        }
    }
}

// ---------------------------------------------------------------------------
template <int WHICH>
__global__ void split_k(const float* __restrict__ src)
{
    __nv_bfloat16* hi = (WHICH == 0) ? g_xhi : (WHICH == 1) ? g_wqhi : g_wohi;
    __nv_bfloat16* lo = (WHICH == 0) ? g_xlo : (WHICH == 1) ? g_wqlo : g_wolo;
    const int i = blockIdx.x * blockDim.x + threadIdx.x;
    float4 v = ((const float4*)src)[i];
    float a[4] = {v.x, v.y, v.z, v.w};
    const int base = i * 4;
#pragma unroll
    for (int j = 0; j < 4; ++j) {
        __nv_bfloat16 h = __float2bfloat16_rn(a[j]);
        hi[base + j] = h;
        lo[base + j] = __float2bfloat16_rn(a[j] - __bfloat162float(h));
    }
}

// qkv fp32 -> compact split-bf16 Q/K
__global__ void conv_qk()
{
    const int idx = blockIdx.x * 256 + threadIdx.x;
    const int row = idx >> 4;
    const int j = (idx & 15) * 4;
    int h, tc, r, off;
    decode_row(row, h, tc, r, off);
    const int tok = off + tc * r;
    const float4 qv = *(const float4*)(g_qkv + (size_t)tok * E3 + h * HD + j);
    const float4 kv = *(const float4*)(g_qkv + (size_t)tok * E3 + EDIM + h * HD + j);
    float qa[4] = {qv.x, qv.y, qv.z, qv.w};
    float ka[4] = {kv.x, kv.y, kv.z, kv.w};
    __nv_bfloat16 qh[4], ql[4], kh[4], kl[4];
#pragma unroll
    for (int t = 0; t < 4; ++t) {
        qh[t] = __float2bfloat16_rn(qa[t]);
        ql[t] = __float2bfloat16_rn(qa[t] - __bfloat162float(qh[t]));
        kh[t] = __float2bfloat16_rn(ka[t]);
        kl[t] = __float2bfloat16_rn(ka[t] - __bfloat162float(kh[t]));
    }
    const size_t o = (size_t)row * HD + j;
    *(uint2*)(g_qchi + o) = *(uint2*)qh;
    *(uint2*)(g_qclo + o) = *(uint2*)ql;
    *(uint2*)(g_kchi + o) = *(uint2*)kh;
    *(uint2*)(g_kclo + o) = *(uint2*)kl;
}

// qkv fp32 V -> compact transposed split-bf16 Vt [head][d][tokc]
__global__ __launch_bounds__(256) void conv_v()
{
    __shared__ float vs[64][65];
    const int tid = threadIdx.x;
    const int row64 = blockIdx.x * 64;
    int h, tc0, r, off;
    decode_row(row64, h, tc0, r, off);
    const int ntokc = (h < 4) ? 8192 : (h < 8) ? 4096 : 2048;
    const int hoff = (h < 4) ? h * 8192 : (h < 8) ? 32768 + (h - 4) * 4096
                                                  : 49152 + (h - 8) * 2048;
    {
        const int tr = tid >> 2;
        const int j = (tid & 3) * 16;
        const int tok = off + (tc0 + tr) * r;
        const float* vp = g_qkv + (size_t)tok * E3 + 2 * EDIM + h * HD + j;
#pragma unroll
        for (int i = 0; i < 4; ++i) {
            float4 v = *(const float4*)(vp + i * 4);
            vs[tr][j + i * 4 + 0] = v.x; vs[tr][j + i * 4 + 1] = v.y;
            vs[tr][j + i * 4 + 2] = v.z; vs[tr][j + i * 4 + 3] = v.w;
        }
    }
    __syncthreads();
    const int d = tid >> 2;
    const int k0 = (tid & 3) * 16;
    __nv_bfloat16 vh[16], vl[16];
#pragma unroll
    for (int i = 0; i < 16; ++i) {
        float v = vs[k0 + i][d];
        vh[i] = __float2bfloat16_rn(v);
        vl[i] = __float2bfloat16_rn(v - __bfloat162float(vh[i]));
    }
    const size_t o = (size_t)hoff * HD + (size_t)d * ntokc + tc0 + k0;
    *(uint4*)(g_vthi + o)     = *(uint4*)vh;
    *(uint4*)(g_vthi + o + 8) = *(uint4*)(vh + 8);
    *(uint4*)(g_vtlo + o)     = *(uint4*)vl;
    *(uint4*)(g_vtlo + o + 8) = *(uint4*)(vl + 8);
}

// ---------------------------------------------------------------------------
// Tensor-core flash attention on compact layouts.
// ---------------------------------------------------------------------------
#define AP 144
#define AKHI 0
#define AKLO 9216
#define AVHI 18432
#define AVLO 27648
#define ASTG 36864

__global__ __launch_bounds__(256, 1) void attn_tc()
{
    extern __shared__ char sm[];
    const int tid = threadIdx.x;
    const int lane = tid & 31;
    const int w = tid >> 5;
    const int g = lane >> 2;
    const int q = lane & 3;

    const int p = blockIdx.y;
    int mseg, hh, grp;
    if (p < 16)      { grp = 0; mseg = p >> 2;        hh = p & 3; }
    else if (p < 24) { grp = 1; mseg = (p - 16) >> 2; hh = (p - 16) & 3; }
    else             { grp = 2; mseg = 0;             hh = p - 24; }
    const int h = grp * 4 + hh;
    const int r = 1 << grp;
    const int off = grp;
    const int ntokc = 8192 >> grp;
    const int hoff = (grp == 0) ? h * 8192 : (grp == 1) ? 32768 + hh * 4096
                                                        : 49152 + hh * 2048;
    const int csegrel = mseg * 2048;
    const int cseg = hoff + csegrel;

    // stage Q (hi->stage0 area, lo->stage1 area): 32 d-elements per thread (FIXED)
    {
        const int row = tid >> 1, hf = tid & 1;
        const size_t go = (size_t)(cseg + blockIdx.x * 128 + row) * HD + hf * 32;
        uint4 a0 = *(const uint4*)(g_qchi + go);
        uint4 a1 = *(const uint4*)(g_qchi + go + 8);
        uint4 a2 = *(const uint4*)(g_qchi + go + 16);
        uint4 a3 = *(const uint4*)(g_qchi + go + 24);
        uint4 b0 = *(const uint4*)(g_qclo + go);
        uint4 b1 = *(const uint4*)(g_qclo + go + 8);
        uint4 b2 = *(const uint4*)(g_qclo + go + 16);
        uint4 b3 = *(const uint4*)(g_qclo + go + 24);
        char* d0 = sm + row * AP + hf * 64;
        char* d1 = sm + ASTG + row * AP + hf * 64;
        *(uint4*)d0        = a0; *(uint4*)(d0 + 16) = a1;
        *(uint4*)(d0 + 32) = a2; *(uint4*)(d0 + 48) = a3;
        *(uint4*)d1        = b0; *(uint4*)(d1 + 16) = b1;
        *(uint4*)(d1 + 32) = b2; *(uint4*)(d1 + 48) = b3;
    }
    __syncthreads();
    uint32_t qhf[4][4], qlf[4][4];
#pragma unroll
    for (int kst = 0; kst < 4; ++kst)
#pragma unroll
        for (int rr = 0; rr < 4; ++rr) {
            const int row = w * 16 + g + 8 * (rr & 1);
            const int col = kst * 16 + q * 2 + 8 * (rr >> 1);
            qhf[kst][rr] = *(const uint32_t*)(sm + row * AP + col * 2);
            qlf[kst][rr] = *(const uint32_t*)(sm + ASTG + row * AP + col * 2);
        }
    __syncthreads();

    const int trow = tid >> 2, tq = tid & 3;
    const __nv_bfloat16* kh = g_kchi + (size_t)(cseg + trow) * HD + tq * 16;
    const __nv_bfloat16* kl = g_kclo + (size_t)(cseg + trow) * HD + tq * 16;
    const size_t vbase = (size_t)hoff * HD + (size_t)trow * ntokc + csegrel + tq * 16;
    const __nv_bfloat16* vh = g_vthi + vbase;
    const __nv_bfloat16* vl = g_vtlo + vbase;
    const uint32_t ts = trow * AP + tq * 32;

    {   // preload tile 0 into stage 0
        char* st = sm;
        *(uint4*)(st + AKHI + ts)      = *(const uint4*)(kh);
        *(uint4*)(st + AKHI + ts + 16) = *(const uint4*)(kh + 8);
        *(uint4*)(st + AKLO + ts)      = *(const uint4*)(kl);
        *(uint4*)(st + AKLO + ts + 16) = *(const uint4*)(kl + 8);
        *(uint4*)(st + AVHI + ts)      = *(const uint4*)(vh);
        *(uint4*)(st + AVHI + ts + 16) = *(const uint4*)(vh + 8);
        *(uint4*)(st + AVLO + ts)      = *(const uint4*)(vl);
        *(uint4*)(st + AVLO + ts + 16) = *(const uint4*)(vl + 8);
    }
    __syncthreads();

    float oacc[8][4];
#pragma unroll
    for (int nd = 0; nd < 8; ++nd)
#pragma unroll
        for (int c = 0; c < 4; ++c) oacc[nd][c] = 0.f;
    float m0 = -CUDART_INF_F, m1 = -CUDART_INF_F, l0 = 0.f, l1 = 0.f;

    for (int kt = 0; kt < 32; ++kt) {
        const char* st = sm + (kt & 1) * ASTG;

        uint4 ra[8];
        if (kt < 31) {
            const int ko = (kt + 1) * 64;
            const size_t kof = (size_t)ko * HD;
            ra[0] = *(const uint4*)(kh + kof); ra[1] = *(const uint4*)(kh + kof + 8);
            ra[2] = *(const uint4*)(kl + kof); ra[3] = *(const uint4*)(kl + kof + 8);
            ra[4] = *(const uint4*)(vh + ko);  ra[5] = *(const uint4*)(vh + ko + 8);
            ra[6] = *(const uint4*)(vl + ko);  ra[7] = *(const uint4*)(vl + ko + 8);
        }

        // S = Q K^T
        float sacc[8][4];
#pragma unroll
        for (int t = 0; t < 8; ++t)
#pragma unroll
            for (int c = 0; c < 4; ++c) sacc[t][c] = 0.f;
#pragma unroll
        for (int kst = 0; kst < 4; ++kst)
#pragma unroll
            for (int ni = 0; ni < 8; ++ni) {
                const char* kb = st + AKHI + (ni * 8 + g) * AP + kst * 32 + q * 4;
                const char* lb = st + AKLO + (ni * 8 + g) * AP + kst * 32 + q * 4;
                uint32_t bh[2] = {*(const uint32_t*)kb, *(const uint32_t*)(kb + 16)};
                uint32_t bl[2] = {*(const uint32_t*)lb, *(const uint32_t*)(lb + 16)};
                mma16816(sacc[ni], qhf[kst], bh);
                mma16816(sacc[ni], qhf[kst], bl);
                mma16816(sacc[ni], qlf[kst], bh);
            }

        // online softmax, base-2
        float rm0 = -CUDART_INF_F, rm1 = -CUDART_INF_F;
#pragma unroll
        for (int t = 0; t < 8; ++t) {
#pragma unroll
            for (int c = 0; c < 4; ++c) sacc[t][c] *= CSC;
            rm0 = fmaxf(rm0, fmaxf(sacc[t][0], sacc[t][1]));
            rm1 = fmaxf(rm1, fmaxf(sacc[t][2], sacc[t][3]));
        }
        rm0 = fmaxf(rm0, __shfl_xor_sync(0xffffffffu, rm0, 1));
        rm0 = fmaxf(rm0, __shfl_xor_sync(0xffffffffu, rm0, 2));
        rm1 = fmaxf(rm1, __shfl_xor_sync(0xffffffffu, rm1, 1));
        rm1 = fmaxf(rm1, __shfl_xor_sync(0xffffffffu, rm1, 2));
        const float mn0 = fmaxf(m0, rm0), mn1 = fmaxf(m1, rm1);
        const float cr0 = exp2_poly(m0 - mn0), cr1 = exp2_poly(m1 - mn1);
        m0 = mn0; m1 = mn1;

        float rs0 = 0.f, rs1 = 0.f;
#pragma unroll
        for (int t = 0; t < 8; ++t) {
            sacc[t][0] = exp2_poly(sacc[t][0] - mn0); rs0 += sacc[t][0];
            sacc[t][1] = exp2_poly(sacc[t][1] - mn0); rs0 += sacc[t][1];
            sacc[t][2] = exp2_poly(sacc[t][2] - mn1); rs1 += sacc[t][2];
            sacc[t][3] = exp2_poly(sacc[t][3] - mn1); rs1 += sacc[t][3];
        }
        rs0 += __shfl_xor_sync(0xffffffffu, rs0, 1);
        rs0 += __shfl_xor_sync(0xffffffffu, rs0, 2);
        rs1 += __shfl_xor_sync(0xffffffffu, rs1, 1);
        rs1 += __shfl_xor_sync(0xffffffffu, rs1, 2);
        l0 = l0 * cr0 + rs0;
        l1 = l1 * cr1 + rs1;
#pragma unroll
        for (int nd = 0; nd < 8; ++nd) {
            oacc[nd][0] *= cr0; oacc[nd][1] *= cr0;
            oacc[nd][2] *= cr1; oacc[nd][3] *= cr1;
        }

        // O += P V   (P from registers; S-frag layout == A-frag layout)
#pragma unroll
        for (int kb = 0; kb < 4; ++kb) {
            uint32_t ah[4], al[4];
#pragma unroll
            for (int half = 0; half < 2; ++half) {
                const float* s0 = sacc[2 * kb + half];
                ah[2 * half]     = pack_bf16x2(s0[1], s0[0]);
                ah[2 * half + 1] = pack_bf16x2(s0[3], s0[2]);
                const float e0 = s0[0] - __uint_as_float(ah[2 * half] << 16);
                const float e1 = s0[1] - __uint_as_float(ah[2 * half] & 0xFFFF0000u);
                const float e2 = s0[2] - __uint_as_float(ah[2 * half + 1] << 16);
                const float e3 = s0[3] - __uint_as_float(ah[2 * half + 1] & 0xFFFF0000u);
                al[2 * half]     = pack_bf16x2(e1, e0);
                al[2 * half + 1] = pack_bf16x2(e3, e2);
            }
#pragma unroll
            for (int nd = 0; nd < 8; ++nd) {
                const char* vb = st + AVHI + (nd * 8 + g) * AP + kb * 32 + q * 4;
                const char* wb = st + AVLO + (nd * 8 + g) * AP + kb * 32 + q * 4;
                uint32_t bh[2] = {*(const uint32_t*)vb, *(const uint32_t*)(vb + 16)};
                uint32_t bl[2] = {*(const uint32_t*)wb, *(const uint32_t*)(wb + 16)};
                mma16816(oacc[nd], ah, bh);
                mma16816(oacc[nd], al, bh);
                mma16816(oacc[nd], ah, bl);
            }
        }

        if (kt < 31) {
            char* dst = sm + ((kt + 1) & 1) * ASTG;
            *(uint4*)(dst + AKHI + ts)      = ra[0];
            *(uint4*)(dst + AKHI + ts + 16) = ra[1];
            *(uint4*)(dst + AKLO + ts)      = ra[2];
            *(uint4*)(dst + AKLO + ts + 16) = ra[3];
            *(uint4*)(dst + AVHI + ts)      = ra[4];
            *(uint4*)(dst + AVHI + ts + 16) = ra[5];
            *(uint4*)(dst + AVLO + ts)      = ra[6];
            *(uint4*)(dst + AVLO + ts + 16) = ra[7];
        }
        __syncthreads();
    }

    // epilogue: normalize and scatter to g_o
    const float inv0 = 1.f / l0, inv1 = 1.f / l1;
    const int ci0 = csegrel + blockIdx.x * 128 + w * 16 + g;
    const int tok0 = off + ci0 * r;
    const int tok1 = off + (ci0 + 8) * r;
    float* o0 = g_o + (size_t)tok0 * EDIM + h * HD + q * 2;
    float* o1 = g_o + (size_t)tok1 * EDIM + h * HD + q * 2;
#pragma unroll
    for (int nd = 0; nd < 8; ++nd) {
        *(float2*)(o0 + nd * 8) = make_float2(oacc[nd][0] * inv0, oacc[nd][1] * inv0);
        *(float2*)(o1 + nd * 8) = make_float2(oacc[nd][2] * inv1, oacc[nd][3] * inv1);
    }
}

// ---------------------------------------------------------------------------
__global__ __launch_bounds__(256) void layernorm_k(
    const float* __restrict__ gamma, const float* __restrict__ beta)
{
    __shared__ float red[8];
    __shared__ float bcast;
    const int row = blockIdx.x;
    const int tid = threadIdx.x;
    const int lane = tid & 31, wid = tid >> 5;
    const float* x = g_o + (size_t)row * EDIM;
    float v0 = x[tid], v1 = x[tid + 256], v2 = x[tid + 512];

    float ssum = v0 + v1 + v2;
#pragma unroll
    for (int w = 16; w >= 1; w >>= 1) ssum += __shfl_xor_sync(0xffffffffu, ssum, w);
    if (lane == 0) red[wid] = ssum;
    __syncthreads();
    if (tid < 32) {
        float t = (tid < 8) ? red[tid] : 0.f;
#pragma unroll
        for (int w = 4; w >= 1; w >>= 1) t += __shfl_xor_sync(0xffffffffu, t, w);
        if (tid == 0) bcast = t;
    }
    __syncthreads();
    const float mu = bcast * (1.f / 768.f);
    float d0 = v0 - mu, d1 = v1 - mu, d2 = v2 - mu;
    float sq = d0 * d0 + d1 * d1 + d2 * d2;
#pragma unroll
    for (int w = 16; w >= 1; w >>= 1) sq += __shfl_xor_sync(0xffffffffu, sq, w);
    __syncthreads();
    if (lane == 0) red[wid] = sq;
    __syncthreads();
    if (tid < 32) {
        float t = (tid < 8) ? red[tid] : 0.f;
#pragma unroll
        for (int w = 4; w >= 1; w >>= 1) t += __shfl_xor_sync(0xffffffffu, t, w);
        if (tid == 0) bcast = t;
    }
    __syncthreads();
    const float rstd = rsqrtf(bcast * (1.f / 768.f) + 1e-5f);
    const size_t rb = (size_t)row * EDIM;
#pragma unroll
    for (int part = 0; part < 3; ++part) {
        const int idx = tid + part * 256;
        const float d = (part == 0) ? d0 : (part == 1) ? d1 : d2;
        const float y = d * rstd * gamma[idx] + beta[idx];
        __nv_bfloat16 h = __float2bfloat16_rn(y);
        g_onhi[rb + idx] = h;
        g_onlo[rb + idx] = __float2bfloat16_rn(y - __bfloat162float(h));
    }
}

__global__ void zero_o() {
    ((float4*)g_o)[blockIdx.x * blockDim.x + threadIdx.x] =
        make_float4(0.f, 0.f, 0.f, 0.f);
}

// ---------------------------------------------------------------------------
extern "C" void kernel_launch(void* const* d_in, const int* in_sizes, int n_in,
                              void* d_out, int out_size)
{
    const float* x      = (const float*)d_in[0];
    const float* w_qkv  = (const float*)d_in[1];
    const float* b_qkv  = (const float*)d_in[2];
    const float* w_out  = (const float*)d_in[3];
    const float* b_out  = (const float*)d_in[4];
    const float* ln_g   = (const float*)d_in[5];
    const float* ln_b   = (const float*)d_in[6];
    float* out = (float*)d_out;

    const int SMEM_GEMM = 2 * STG_B;      // 80 KB
    const int SMEM_ATTN = 2 * ASTG;       // 72 KB
    cudaFuncSetAttribute(wgemm<0>, cudaFuncAttributeMaxDynamicSharedMemorySize, SMEM_GEMM);
    cudaFuncSetAttribute(wgemm<1>, cudaFuncAttributeMaxDynamicSharedMemorySize, SMEM_GEMM);
    cudaFuncSetAttribute(attn_tc, cudaFuncAttributeMaxDynamicSharedMemorySize, SMEM_ATTN);

    split_k<0><<<(NTOK * EDIM / 4) / 256, 256>>>(x);
    split_k<1><<<(E3 * EDIM / 4) / 256, 256>>>(w_qkv);
    split_k<2><<<(EDIM * EDIM / 4) / 256, 256>>>(w_out);

    dim3 g1(E3 / 128, NTOK / 128);
    wgemm<0><<<g1, 256, SMEM_GEMM>>>(b_qkv, nullptr);

    conv_qk<<<(NCROWS * 16) / 256, 256>>>();
    conv_v<<<NCROWS / 64, 256>>>();
    zero_o<<<(NTOK * EDIM / 4) / 256, 256>>>();

    dim3 g2(16, 28);
    attn_tc<<<g2, 256, SMEM_ATTN>>>();

    layernorm_k<<<NTOK, 256>>>(ln_g, ln_b);

    dim3 g3(EDIM / 128, NTOK / 128);
    wgemm<1><<<g3, 256, SMEM_GEMM>>>(b_out, out);
}

// round 10
// speedup vs baseline: 1.8470x; 1.0019x over previous
#include <cuda_runtime.h>
#include <cuda_bf16.h>
#include <math_constants.h>
#include <cstdint>

#define NTOK 8192
#define EDIM 768
#define E3   2304
#define HD   64
#define CSC  0.18033688011112042f   // 0.125 * log2(e)
#define NCROWS 57344                // 4*8192 + 4*4096 + 4*2048

__device__ float g_qkv[NTOK * E3];
__device__ float g_o[NTOK * EDIM];
__device__ __nv_bfloat16 g_xhi[NTOK * EDIM];
__device__ __nv_bfloat16 g_xlo[NTOK * EDIM];
__device__ __nv_bfloat16 g_wqhi[E3 * EDIM];
__device__ __nv_bfloat16 g_wqlo[E3 * EDIM];
__device__ __nv_bfloat16 g_wohi[EDIM * EDIM];
__device__ __nv_bfloat16 g_wolo[EDIM * EDIM];
__device__ __nv_bfloat16 g_onhi[NTOK * EDIM];
__device__ __nv_bfloat16 g_onlo[NTOK * EDIM];
__device__ __nv_bfloat16 g_qchi[NCROWS * HD];
__device__ __nv_bfloat16 g_qclo[NCROWS * HD];
__device__ __nv_bfloat16 g_kchi[NCROWS * HD];
__device__ __nv_bfloat16 g_kclo[NCROWS * HD];
__device__ __nv_bfloat16 g_vthi[NCROWS * HD];  // [head][d][tokc]
__device__ __nv_bfloat16 g_vtlo[NCROWS * HD];

__device__ __forceinline__ void mma16816(float* c, const uint32_t* a, const uint32_t* b)
{
    asm volatile(
        "mma.sync.aligned.m16n8k16.row.col.f32.bf16.bf16.f32 "
        "{%0,%1,%2,%3}, {%4,%5,%6,%7}, {%8,%9}, {%0,%1,%2,%3};"
        : "+f"(c[0]), "+f"(c[1]), "+f"(c[2]), "+f"(c[3])
        : "r"(a[0]), "r"(a[1]), "r"(a[2]), "r"(a[3]), "r"(b[0]), "r"(b[1]));
}

__device__ __forceinline__ void ldmx4(uint32_t& r0, uint32_t& r1, uint32_t& r2,
                                      uint32_t& r3, uint32_t addr)
{
    asm volatile("ldmatrix.sync.aligned.m8n8.x4.shared.b16 {%0,%1,%2,%3}, [%4];"
                 : "=r"(r0), "=r"(r1), "=r"(r2), "=r"(r3) : "r"(addr));
}

__device__ __forceinline__ uint32_t smem_u32(const void* p)
{
    uint32_t a;
    asm("{ .reg .u64 t; cvta.to.shared.u64 t, %1; cvt.u32.u64 %0, t; }"
        : "=r"(a) : "l"(p));
    return a;
}

__device__ __forceinline__ float exp2_poly(float t)
{
    t = fmaxf(t, -125.f);
    float ft = floorf(t);
    float f = t - ft;
    float p = 1.5403530e-4f;
    p = fmaf(p, f, 1.3333558e-3f);
    p = fmaf(p, f, 9.6181291e-3f);
    p = fmaf(p, f, 5.5504109e-2f);
    p = fmaf(p, f, 2.4022651e-1f);
    p = fmaf(p, f, 6.9314718e-1f);
    p = fmaf(p, f, 1.0f);
    return __int_as_float(__float_as_int(p) + (((int)ft) << 23));
}

__device__ __forceinline__ uint32_t pack_bf16x2(float odd, float even)
{
    uint32_t d;
    asm("cvt.rn.bf16x2.f32 %0, %1, %2;" : "=r"(d) : "f"(odd), "f"(even));
    return d;
}

__device__ __forceinline__ void decode_row(int row, int& h, int& tc, int& r, int& off)
{
    if (row < 32768)      { h = row >> 13;                tc = row & 8191; r = 1; off = 0; }
    else if (row < 49152) { int u = row - 32768; h = 4 + (u >> 12); tc = u & 4095; r = 2; off = 1; }
    else                  { int u = row - 49152; h = 8 + (u >> 11); tc = u & 2047; r = 4; off = 2; }
}

// ---------------------------------------------------------------------------
// wgemm: split-bf16 HMMA GEMM, C = A @ B^T + bias.  Fragment loads via
// ldmatrix.x4 (12 instr/k0 instead of 48 LDS.32) — pitch-80 rows verified
// conflict-free for 8-lane ldmatrix phases.
// ---------------------------------------------------------------------------
#define TILE_B 10240
#define STG_B  40960

template <int MODE>
__global__ __launch_bounds__(256) void wgemm(const float* __restrict__ bias,
                                             float* __restrict__ Cout)
{
    constexpr int NTOT = (MODE == 0) ? E3 : EDIM;
    constexpr int NC = 24;
    extern __shared__ char smem[];

    const int tid = threadIdx.x;
    const int lane = tid & 31;
    const int wid = tid >> 5;
    const int rowBase = blockIdx.y << 7;
    const int colBase = blockIdx.x << 7;
    const int mBase = (wid & 1) * 64;
    const int nBase = (wid >> 1) * 32;

    const __nv_bfloat16* Ahi = (MODE == 0) ? g_xhi : g_onhi;
    const __nv_bfloat16* Alo = (MODE == 0) ? g_xlo : g_onlo;
    const __nv_bfloat16* Bhi = (MODE == 0) ? g_wqhi : g_wohi;
    const __nv_bfloat16* Blo = (MODE == 0) ? g_wqlo : g_wolo;
    float* C = (MODE == 0) ? g_qkv : Cout;

    const int lr = tid >> 1;
    const int lh = tid & 1;
    const __nv_bfloat16* gA0 = Ahi + (size_t)(rowBase + lr) * EDIM + lh * 16;
    const __nv_bfloat16* gA1 = Alo + (size_t)(rowBase + lr) * EDIM + lh * 16;
    const __nv_bfloat16* gB0 = Bhi + (size_t)(colBase + lr) * EDIM + lh * 16;
    const __nv_bfloat16* gB1 = Blo + (size_t)(colBase + lr) * EDIM + lh * 16;
    const uint32_t soff = (uint32_t)(lr * 80 + lh * 32);

    const uint32_t smbase = smem_u32(smem);
    const int laneR = lane & 15;
    const int laneH = (lane >> 4) * 16;

    float acc[4][4][4];
#pragma unroll
    for (int mi = 0; mi < 4; ++mi)
#pragma unroll
        for (int ni = 0; ni < 4; ++ni)
#pragma unroll
            for (int r = 0; r < 4; ++r) acc[mi][ni][r] = 0.f;

    {
        char* st = smem;
        *(uint4*)(st + 0 * TILE_B + soff)      = *(const uint4*)(gA0);
        *(uint4*)(st + 0 * TILE_B + soff + 16) = *(const uint4*)(gA0 + 8);
        *(uint4*)(st + 1 * TILE_B + soff)      = *(const uint4*)(gA1);
        *(uint4*)(st + 1 * TILE_B + soff + 16) = *(const uint4*)(gA1 + 8);
        *(uint4*)(st + 2 * TILE_B + soff)      = *(const uint4*)(gB0);
        *(uint4*)(st + 2 * TILE_B + soff + 16) = *(const uint4*)(gB0 + 8);
        *(uint4*)(st + 3 * TILE_B + soff)      = *(const uint4*)(gB1);
        *(uint4*)(st + 3 * TILE_B + soff + 16) = *(const uint4*)(gB1 + 8);
    }
    __syncthreads();

    const int g = lane >> 2;
    const int q = lane & 3;

    for (int c = 0; c < NC; ++c) {
        const int stg = c & 1;
        uint4 ra[8];
        if (c + 1 < NC) {
            const int off = (c + 1) * 32;
            ra[0] = *(const uint4*)(gA0 + off); ra[1] = *(const uint4*)(gA0 + off + 8);
            ra[2] = *(const uint4*)(gA1 + off); ra[3] = *(const uint4*)(gA1 + off + 8);
            ra[4] = *(const uint4*)(gB0 + off); ra[5] = *(const uint4*)(gB0 + off + 8);
            ra[6] = *(const uint4*)(gB1 + off); ra[7] = *(const uint4*)(gB1 + off + 8);
        }

        const uint32_t As = smbase + stg * STG_B;
#pragma unroll
        for (int k0 = 0; k0 < 32; k0 += 16) {
            uint32_t ahi[4][4], alo[4][4];
#pragma unroll
            for (int mi = 0; mi < 4; ++mi) {
                const uint32_t ad = As + (uint32_t)((mBase + mi * 16 + laneR) * 80
                                                    + k0 * 2 + laneH);
                ldmx4(ahi[mi][0], ahi[mi][1], ahi[mi][2], ahi[mi][3], ad);
                ldmx4(alo[mi][0], alo[mi][1], alo[mi][2], alo[mi][3], ad + TILE_B);
            }
            uint32_t bhi[4][2], blo[4][2];
#pragma unroll
            for (int np = 0; np < 2; ++np) {
                const uint32_t bd = As + 2 * TILE_B
                                  + (uint32_t)((nBase + np * 16 + laneR) * 80
                                               + k0 * 2 + laneH);
                uint32_t r0, r1, r2, r3;
                ldmx4(r0, r1, r2, r3, bd);
                bhi[2 * np][0] = r0; bhi[2 * np][1] = r2;
                bhi[2 * np + 1][0] = r1; bhi[2 * np + 1][1] = r3;
                ldmx4(r0, r1, r2, r3, bd + TILE_B);
                blo[2 * np][0] = r0; blo[2 * np][1] = r2;
                blo[2 * np + 1][0] = r1; blo[2 * np + 1][1] = r3;
            }
#pragma unroll
            for (int mi = 0; mi < 4; ++mi)
#pragma unroll
                for (int ni = 0; ni < 4; ++ni) {
                    mma16816(acc[mi][ni], ahi[mi], bhi[ni]);
                    mma16816(acc[mi][ni], ahi[mi], blo[ni]);
                    mma16816(acc[mi][ni], alo[mi], bhi[ni]);
                }
        }

        if (c + 1 < NC) {
            char* st = smem + ((c + 1) & 1) * STG_B;
            *(uint4*)(st + 0 * TILE_B + soff)      = ra[0];
            *(uint4*)(st + 0 * TILE_B + soff + 16) = ra[1];
            *(uint4*)(st + 1 * TILE_B + soff)      = ra[2];
            *(uint4*)(st + 1 * TILE_B + soff + 16) = ra[3];
            *(uint4*)(st + 2 * TILE_B + soff)      = ra[4];
            *(uint4*)(st + 2 * TILE_B + soff + 16) = ra[5];
            *(uint4*)(st + 3 * TILE_B + soff)      = ra[6];
            *(uint4*)(st + 3 * TILE_B + soff + 16) = ra[7];
        }
        __syncthreads();
    }

#pragma unroll
    for (int mi = 0; mi < 4; ++mi) {
        const int row0 = rowBase + mBase + mi * 16 + g;
#pragma unroll
        for (int ni = 0; ni < 4; ++ni) {
            const int colg = colBase + nBase + ni * 8 + q * 2;
            const float b0 = bias[colg], b1 = bias[colg + 1];
            float* c0 = C + (size_t)row0 * NTOT + colg;
            float* c1 = C + (size_t)(row0 + 8) * NTOT + colg;
            c0[0] = acc[mi][ni][0] + b0; c0[1] = acc[mi][ni][1] + b1;
            c1[0] = acc[mi][ni][2] + b0; c1[1] = acc[mi][ni][3] + b1;
        }
    }
}

// ---------------------------------------------------------------------------
template <int WHICH>
__global__ void split_k(const float* __restrict__ src)
{
    __nv_bfloat16* hi = (WHICH == 0) ? g_xhi : (WHICH == 1) ? g_wqhi : g_wohi;
    __nv_bfloat16* lo = (WHICH == 0) ? g_xlo : (WHICH == 1) ? g_wqlo : g_wolo;
    const int i = blockIdx.x * blockDim.x + threadIdx.x;
    float4 v = ((const float4*)src)[i];
    float a[4] = {v.x, v.y, v.z, v.w};
    const int base = i * 4;
#pragma unroll
    for (int j = 0; j < 4; ++j) {
        __nv_bfloat16 h = __float2bfloat16_rn(a[j]);
        hi[base + j] = h;
        lo[base + j] = __float2bfloat16_rn(a[j] - __bfloat162float(h));
    }
}

// qkv fp32 -> compact split-bf16 Q/K
__global__ void conv_qk()
{
    const int idx = blockIdx.x * 256 + threadIdx.x;
    const int row = idx >> 4;
    const int j = (idx & 15) * 4;
    int h, tc, r, off;
    decode_row(row, h, tc, r, off);
    const int tok = off + tc * r;
    const float4 qv = *(const float4*)(g_qkv + (size_t)tok * E3 + h * HD + j);
    const float4 kv = *(const float4*)(g_qkv + (size_t)tok * E3 + EDIM + h * HD + j);
    float qa[4] = {qv.x, qv.y, qv.z, qv.w};
    float ka[4] = {kv.x, kv.y, kv.z, kv.w};
    __nv_bfloat16 qh[4], ql[4], kh[4], kl[4];
#pragma unroll
    for (int t = 0; t < 4; ++t) {
        qh[t] = __float2bfloat16_rn(qa[t]);
        ql[t] = __float2bfloat16_rn(qa[t] - __bfloat162float(qh[t]));
        kh[t] = __float2bfloat16_rn(ka[t]);
        kl[t] = __float2bfloat16_rn(ka[t] - __bfloat162float(kh[t]));
    }
    const size_t o = (size_t)row * HD + j;
    *(uint2*)(g_qchi + o) = *(uint2*)qh;
    *(uint2*)(g_qclo + o) = *(uint2*)ql;
    *(uint2*)(g_kchi + o) = *(uint2*)kh;
    *(uint2*)(g_kclo + o) = *(uint2*)kl;
}

// qkv fp32 V -> compact transposed split-bf16 Vt [head][d][tokc]
__global__ __launch_bounds__(256) void conv_v()
{
    __shared__ float vs[64][65];
    const int tid = threadIdx.x;
    const int row64 = blockIdx.x * 64;
    int h, tc0, r, off;
    decode_row(row64, h, tc0, r, off);
    const int ntokc = (h < 4) ? 8192 : (h < 8) ? 4096 : 2048;
    const int hoff = (h < 4) ? h * 8192 : (h < 8) ? 32768 + (h - 4) * 4096
                                                  : 49152 + (h - 8) * 2048;
    {
        const int tr = tid >> 2;
        const int j = (tid & 3) * 16;
        const int tok = off + (tc0 + tr) * r;
        const float* vp = g_qkv + (size_t)tok * E3 + 2 * EDIM + h * HD + j;
#pragma unroll
        for (int i = 0; i < 4; ++i) {
            float4 v = *(const float4*)(vp + i * 4);
            vs[tr][j + i * 4 + 0] = v.x; vs[tr][j + i * 4 + 1] = v.y;
            vs[tr][j + i * 4 + 2] = v.z; vs[tr][j + i * 4 + 3] = v.w;
        }
    }
    __syncthreads();
    const int d = tid >> 2;
    const int k0 = (tid & 3) * 16;
    __nv_bfloat16 vh[16], vl[16];
#pragma unroll
    for (int i = 0; i < 16; ++i) {
        float v = vs[k0 + i][d];
        vh[i] = __float2bfloat16_rn(v);
        vl[i] = __float2bfloat16_rn(v - __bfloat162float(vh[i]));
    }
    const size_t o = (size_t)hoff * HD + (size_t)d * ntokc + tc0 + k0;
    *(uint4*)(g_vthi + o)     = *(uint4*)vh;
    *(uint4*)(g_vthi + o + 8) = *(uint4*)(vh + 8);
    *(uint4*)(g_vtlo + o)     = *(uint4*)vl;
    *(uint4*)(g_vtlo + o + 8) = *(uint4*)(vl + 8);
}

// ---------------------------------------------------------------------------
// Tensor-core flash attention on compact layouts (unchanged from R9 pass).
// ---------------------------------------------------------------------------
#define AP 144
#define AKHI 0
#define AKLO 9216
#define AVHI 18432
#define AVLO 27648
#define ASTG 36864

__global__ __launch_bounds__(256, 1) void attn_tc()
{
    extern __shared__ char sm[];
    const int tid = threadIdx.x;
    const int lane = tid & 31;
    const int w = tid >> 5;
    const int g = lane >> 2;
    const int q = lane & 3;

    const int p = blockIdx.y;
    int mseg, hh, grp;
    if (p < 16)      { grp = 0; mseg = p >> 2;        hh = p & 3; }
    else if (p < 24) { grp = 1; mseg = (p - 16) >> 2; hh = (p - 16) & 3; }
    else             { grp = 2; mseg = 0;             hh = p - 24; }
    const int h = grp * 4 + hh;
    const int r = 1 << grp;
    const int off = grp;
    const int ntokc = 8192 >> grp;
    const int hoff = (grp == 0) ? h * 8192 : (grp == 1) ? 32768 + hh * 4096
                                                        : 49152 + hh * 2048;
    const int csegrel = mseg * 2048;
    const int cseg = hoff + csegrel;

    // stage Q (hi->stage0 area, lo->stage1 area): 32 d-elements per thread
    {
        const int row = tid >> 1, hf = tid & 1;
        const size_t go = (size_t)(cseg + blockIdx.x * 128 + row) * HD + hf * 32;
        uint4 a0 = *(const uint4*)(g_qchi + go);
        uint4 a1 = *(const uint4*)(g_qchi + go + 8);
        uint4 a2 = *(const uint4*)(g_qchi + go + 16);
        uint4 a3 = *(const uint4*)(g_qchi + go + 24);
        uint4 b0 = *(const uint4*)(g_qclo + go);
        uint4 b1 = *(const uint4*)(g_qclo + go + 8);
        uint4 b2 = *(const uint4*)(g_qclo + go + 16);
        uint4 b3 = *(const uint4*)(g_qclo + go + 24);
        char* d0 = sm + row * AP + hf * 64;
        char* d1 = sm + ASTG + row * AP + hf * 64;
        *(uint4*)d0        = a0; *(uint4*)(d0 + 16) = a1;
        *(uint4*)(d0 + 32) = a2; *(uint4*)(d0 + 48) = a3;
        *(uint4*)d1        = b0; *(uint4*)(d1 + 16) = b1;
        *(uint4*)(d1 + 32) = b2; *(uint4*)(d1 + 48) = b3;
    }
    __syncthreads();
    uint32_t qhf[4][4], qlf[4][4];
#pragma unroll
    for (int kst = 0; kst < 4; ++kst)
#pragma unroll
        for (int rr = 0; rr < 4; ++rr) {
            const int row = w * 16 + g + 8 * (rr & 1);
            const int col = kst * 16 + q * 2 + 8 * (rr >> 1);
            qhf[kst][rr] = *(const uint32_t*)(sm + row * AP + col * 2);
            qlf[kst][rr] = *(const uint32_t*)(sm + ASTG + row * AP + col * 2);
        }
    __syncthreads();

    const int trow = tid >> 2, tq = tid & 3;
    const __nv_bfloat16* kh = g_kchi + (size_t)(cseg + trow) * HD + tq * 16;
    const __nv_bfloat16* kl = g_kclo + (size_t)(cseg + trow) * HD + tq * 16;
    const size_t vbase = (size_t)hoff * HD + (size_t)trow * ntokc + csegrel + tq * 16;
    const __nv_bfloat16* vh = g_vthi + vbase;
    const __nv_bfloat16* vl = g_vtlo + vbase;
    const uint32_t ts = trow * AP + tq * 32;

    {   // preload tile 0 into stage 0
        char* st = sm;
        *(uint4*)(st + AKHI + ts)      = *(const uint4*)(kh);
        *(uint4*)(st + AKHI + ts + 16) = *(const uint4*)(kh + 8);
        *(uint4*)(st + AKLO + ts)      = *(const uint4*)(kl);
        *(uint4*)(st + AKLO + ts + 16) = *(const uint4*)(kl + 8);
        *(uint4*)(st + AVHI + ts)      = *(const uint4*)(vh);
        *(uint4*)(st + AVHI + ts + 16) = *(const uint4*)(vh + 8);
        *(uint4*)(st + AVLO + ts)      = *(const uint4*)(vl);
        *(uint4*)(st + AVLO + ts + 16) = *(const uint4*)(vl + 8);
    }
    __syncthreads();

    float oacc[8][4];
#pragma unroll
    for (int nd = 0; nd < 8; ++nd)
#pragma unroll
        for (int c = 0; c < 4; ++c) oacc[nd][c] = 0.f;
    float m0 = -CUDART_INF_F, m1 = -CUDART_INF_F, l0 = 0.f, l1 = 0.f;

    for (int kt = 0; kt < 32; ++kt) {
        const char* st = sm + (kt & 1) * ASTG;

        uint4 ra[8];
        if (kt < 31) {
            const int ko = (kt + 1) * 64;
            const size_t kof = (size_t)ko * HD;
            ra[0] = *(const uint4*)(kh + kof); ra[1] = *(const uint4*)(kh + kof + 8);
            ra[2] = *(const uint4*)(kl + kof); ra[3] = *(const uint4*)(kl + kof + 8);
            ra[4] = *(const uint4*)(vh + ko);  ra[5] = *(const uint4*)(vh + ko + 8);
            ra[6] = *(const uint4*)(vl + ko);  ra[7] = *(const uint4*)(vl + ko + 8);
        }

        // S = Q K^T
        float sacc[8][4];
#pragma unroll
        for (int t = 0; t < 8; ++t)
#pragma unroll
            for (int c = 0; c < 4; ++c) sacc[t][c] = 0.f;
#pragma unroll
        for (int kst = 0; kst < 4; ++kst)
#pragma unroll
            for (int ni = 0; ni < 8; ++ni) {
                const char* kb = st + AKHI + (ni * 8 + g) * AP + kst * 32 + q * 4;
                const char* lb = st + AKLO + (ni * 8 + g) * AP + kst * 32 + q * 4;
                uint32_t bh[2] = {*(const uint32_t*)kb, *(const uint32_t*)(kb + 16)};
                uint32_t bl[2] = {*(const uint32_t*)lb, *(const uint32_t*)(lb + 16)};
                mma16816(sacc[ni], qhf[kst], bh);
                mma16816(sacc[ni], qhf[kst], bl);
                mma16816(sacc[ni], qlf[kst], bh);
            }

        // online softmax, base-2
        float rm0 = -CUDART_INF_F, rm1 = -CUDART_INF_F;
#pragma unroll
        for (int t = 0; t < 8; ++t) {
#pragma unroll
            for (int c = 0; c < 4; ++c) sacc[t][c] *= CSC;
            rm0 = fmaxf(rm0, fmaxf(sacc[t][0], sacc[t][1]));
            rm1 = fmaxf(rm1, fmaxf(sacc[t][2], sacc[t][3]));
        }
        rm0 = fmaxf(rm0, __shfl_xor_sync(0xffffffffu, rm0, 1));
        rm0 = fmaxf(rm0, __shfl_xor_sync(0xffffffffu, rm0, 2));
        rm1 = fmaxf(rm1, __shfl_xor_sync(0xffffffffu, rm1, 1));
        rm1 = fmaxf(rm1, __shfl_xor_sync(0xffffffffu, rm1, 2));
        const float mn0 = fmaxf(m0, rm0), mn1 = fmaxf(m1, rm1);
        const float cr0 = exp2_poly(m0 - mn0), cr1 = exp2_poly(m1 - mn1);
        m0 = mn0; m1 = mn1;

        float rs0 = 0.f, rs1 = 0.f;
#pragma unroll
        for (int t = 0; t < 8; ++t) {
            sacc[t][0] = exp2_poly(sacc[t][0] - mn0); rs0 += sacc[t][0];
            sacc[t][1] = exp2_poly(sacc[t][1] - mn0); rs0 += sacc[t][1];
            sacc[t][2] = exp2_poly(sacc[t][2] - mn1); rs1 += sacc[t][2];
            sacc[t][3] = exp2_poly(sacc[t][3] - mn1); rs1 += sacc[t][3];
        }
        rs0 += __shfl_xor_sync(0xffffffffu, rs0, 1);
        rs0 += __shfl_xor_sync(0xffffffffu, rs0, 2);
        rs1 += __shfl_xor_sync(0xffffffffu, rs1, 1);
        rs1 += __shfl_xor_sync(0xffffffffu, rs1, 2);
        l0 = l0 * cr0 + rs0;
        l1 = l1 * cr1 + rs1;
#pragma unroll
        for (int nd = 0; nd < 8; ++nd) {
            oacc[nd][0] *= cr0; oacc[nd][1] *= cr0;
            oacc[nd][2] *= cr1; oacc[nd][3] *= cr1;
        }

        // O += P V   (P from registers; S-frag layout == A-frag layout)
#pragma unroll
        for (int kb = 0; kb < 4; ++kb) {
            uint32_t ah[4], al[4];
#pragma unroll
            for (int half = 0; half < 2; ++half) {
                const float* s0 = sacc[2 * kb + half];
                ah[2 * half]     = pack_bf16x2(s0[1], s0[0]);
                ah[2 * half + 1] = pack_bf16x2(s0[3], s0[2]);
                const float e0 = s0[0] - __uint_as_float(ah[2 * half] << 16);
                const float e1 = s0[1] - __uint_as_float(ah[2 * half] & 0xFFFF0000u);
                const float e2 = s0[2] - __uint_as_float(ah[2 * half + 1] << 16);
                const float e3 = s0[3] - __uint_as_float(ah[2 * half + 1] & 0xFFFF0000u);
                al[2 * half]     = pack_bf16x2(e1, e0);
                al[2 * half + 1] = pack_bf16x2(e3, e2);
            }
#pragma unroll
            for (int nd = 0; nd < 8; ++nd) {
                const char* vb = st + AVHI + (nd * 8 + g) * AP + kb * 32 + q * 4;
                const char* wb = st + AVLO + (nd * 8 + g) * AP + kb * 32 + q * 4;
                uint32_t bh[2] = {*(const uint32_t*)vb, *(const uint32_t*)(vb + 16)};
                uint32_t bl[2] = {*(const uint32_t*)wb, *(const uint32_t*)(wb + 16)};
                mma16816(oacc[nd], ah, bh);
                mma16816(oacc[nd], al, bh);
                mma16816(oacc[nd], ah, bl);
            }
        }

        if (kt < 31) {
            char* dst = sm + ((kt + 1) & 1) * ASTG;
            *(uint4*)(dst + AKHI + ts)      = ra[0];
            *(uint4*)(dst + AKHI + ts + 16) = ra[1];
            *(uint4*)(dst + AKLO + ts)      = ra[2];
            *(uint4*)(dst + AKLO + ts + 16) = ra[3];
            *(uint4*)(dst + AVHI + ts)      = ra[4];
            *(uint4*)(dst + AVHI + ts + 16) = ra[5];
            *(uint4*)(dst + AVLO + ts)      = ra[6];
            *(uint4*)(dst + AVLO + ts + 16) = ra[7];
        }
        __syncthreads();
    }

    // epilogue: normalize and scatter to g_o
    const float inv0 = 1.f / l0, inv1 = 1.f / l1;
    const int ci0 = csegrel + blockIdx.x * 128 + w * 16 + g;
    const int tok0 = off + ci0 * r;
    const int tok1 = off + (ci0 + 8) * r;
    float* o0 = g_o + (size_t)tok0 * EDIM + h * HD + q * 2;
    float* o1 = g_o + (size_t)tok1 * EDIM + h * HD + q * 2;
#pragma unroll
    for (int nd = 0; nd < 8; ++nd) {
        *(float2*)(o0 + nd * 8) = make_float2(oacc[nd][0] * inv0, oacc[nd][1] * inv0);
        *(float2*)(o1 + nd * 8) = make_float2(oacc[nd][2] * inv1, oacc[nd][3] * inv1);
    }
}

// ---------------------------------------------------------------------------
__global__ __launch_bounds__(256) void layernorm_k(
    const float* __restrict__ gamma, const float* __restrict__ beta)
{
    __shared__ float red[8];
    __shared__ float bcast;
    const int row = blockIdx.x;
    const int tid = threadIdx.x;
    const int lane = tid & 31, wid = tid >> 5;
    const float* x = g_o + (size_t)row * EDIM;
    float v0 = x[tid], v1 = x[tid + 256], v2 = x[tid + 512];

    float ssum = v0 + v1 + v2;
#pragma unroll
    for (int w = 16; w >= 1; w >>= 1) ssum += __shfl_xor_sync(0xffffffffu, ssum, w);
    if (lane == 0) red[wid] = ssum;
    __syncthreads();
    if (tid < 32) {
        float t = (tid < 8) ? red[tid] : 0.f;
#pragma unroll
        for (int w = 4; w >= 1; w >>= 1) t += __shfl_xor_sync(0xffffffffu, t, w);
        if (tid == 0) bcast = t;
    }
    __syncthreads();
    const float mu = bcast * (1.f / 768.f);
    float d0 = v0 - mu, d1 = v1 - mu, d2 = v2 - mu;
    float sq = d0 * d0 + d1 * d1 + d2 * d2;
#pragma unroll
    for (int w = 16; w >= 1; w >>= 1) sq += __shfl_xor_sync(0xffffffffu, sq, w);
    __syncthreads();
    if (lane == 0) red[wid] = sq;
    __syncthreads();
    if (tid < 32) {
        float t = (tid < 8) ? red[tid] : 0.f;
#pragma unroll
        for (int w = 4; w >= 1; w >>= 1) t += __shfl_xor_sync(0xffffffffu, t, w);
        if (tid == 0) bcast = t;
    }
    __syncthreads();
    const float rstd = rsqrtf(bcast * (1.f / 768.f) + 1e-5f);
    const size_t rb = (size_t)row * EDIM;
#pragma unroll
    for (int part = 0; part < 3; ++part) {
        const int idx = tid + part * 256;
        const float d = (part == 0) ? d0 : (part == 1) ? d1 : d2;
        const float y = d * rstd * gamma[idx] + beta[idx];
        __nv_bfloat16 h = __float2bfloat16_rn(y);
        g_onhi[rb + idx] = h;
        g_onlo[rb + idx] = __float2bfloat16_rn(y - __bfloat162float(h));
    }
}

__global__ void zero_o() {
    ((float4*)g_o)[blockIdx.x * blockDim.x + threadIdx.x] =
        make_float4(0.f, 0.f, 0.f, 0.f);
}

// ---------------------------------------------------------------------------
extern "C" void kernel_launch(void* const* d_in, const int* in_sizes, int n_in,
                              void* d_out, int out_size)
{
    const float* x      = (const float*)d_in[0];
    const float* w_qkv  = (const float*)d_in[1];
    const float* b_qkv  = (const float*)d_in[2];
    const float* w_out  = (const float*)d_in[3];
    const float* b_out  = (const float*)d_in[4];
    const float* ln_g   = (const float*)d_in[5];
    const float* ln_b   = (const float*)d_in[6];
    float* out = (float*)d_out;

    const int SMEM_GEMM = 2 * STG_B;      // 80 KB
    const int SMEM_ATTN = 2 * ASTG;       // 72 KB
    cudaFuncSetAttribute(wgemm<0>, cudaFuncAttributeMaxDynamicSharedMemorySize, SMEM_GEMM);
    cudaFuncSetAttribute(wgemm<1>, cudaFuncAttributeMaxDynamicSharedMemorySize, SMEM_GEMM);
    cudaFuncSetAttribute(attn_tc, cudaFuncAttributeMaxDynamicSharedMemorySize, SMEM_ATTN);

    split_k<0><<<(NTOK * EDIM / 4) / 256, 256>>>(x);
    split_k<1><<<(E3 * EDIM / 4) / 256, 256>>>(w_qkv);
    split_k<2><<<(EDIM * EDIM / 4) / 256, 256>>>(w_out);

    dim3 g1(E3 / 128, NTOK / 128);
    wgemm<0><<<g1, 256, SMEM_GEMM>>>(b_qkv, nullptr);

    conv_qk<<<(NCROWS * 16) / 256, 256>>>();
    conv_v<<<NCROWS / 64, 256>>>();
    zero_o<<<(NTOK * EDIM / 4) / 256, 256>>>();

    dim3 g2(16, 28);
    attn_tc<<<g2, 256, SMEM_ATTN>>>();

    layernorm_k<<<NTOK, 256>>>(ln_g, ln_b);

    dim3 g3(EDIM / 128, NTOK / 128);
    wgemm<1><<<g3, 256, SMEM_GEMM>>>(b_out, out);
}

// round 15
// speedup vs baseline: 1.9443x; 1.0527x over previous
#include <cuda_runtime.h>
#include <cuda_bf16.h>
#include <math_constants.h>
#include <cstdint>

#define NTOK 8192
#define EDIM 768
#define E3   2304
#define HD   64
#define CSC  0.18033688011112042f   // 0.125 * log2(e)
#define NCROWS 57344                // 4*8192 + 4*4096 + 4*2048

__device__ float g_qkv[NTOK * E3];
__device__ float g_o[NTOK * EDIM];
__device__ __nv_bfloat16 g_xhi[NTOK * EDIM];
__device__ __nv_bfloat16 g_xlo[NTOK * EDIM];
__device__ __nv_bfloat16 g_wqhi[E3 * EDIM];
__device__ __nv_bfloat16 g_wqlo[E3 * EDIM];
__device__ __nv_bfloat16 g_wohi[EDIM * EDIM];
__device__ __nv_bfloat16 g_wolo[EDIM * EDIM];
__device__ __nv_bfloat16 g_onhi[NTOK * EDIM];
__device__ __nv_bfloat16 g_onlo[NTOK * EDIM];
__device__ __nv_bfloat16 g_qchi[NCROWS * HD];
__device__ __nv_bfloat16 g_qclo[NCROWS * HD];
__device__ __nv_bfloat16 g_kchi[NCROWS * HD];
__device__ __nv_bfloat16 g_kclo[NCROWS * HD];
__device__ __nv_bfloat16 g_vthi[NCROWS * HD];  // [head][d][tokc]
__device__ __nv_bfloat16 g_vtlo[NCROWS * HD];

__device__ __forceinline__ void mma16816(float* c, const uint32_t* a, const uint32_t* b)
{
    asm volatile(
        "mma.sync.aligned.m16n8k16.row.col.f32.bf16.bf16.f32 "
        "{%0,%1,%2,%3}, {%4,%5,%6,%7}, {%8,%9}, {%0,%1,%2,%3};"
        : "+f"(c[0]), "+f"(c[1]), "+f"(c[2]), "+f"(c[3])
        : "r"(a[0]), "r"(a[1]), "r"(a[2]), "r"(a[3]), "r"(b[0]), "r"(b[1]));
}

__device__ __forceinline__ void ldmx4(uint32_t& r0, uint32_t& r1, uint32_t& r2,
                                      uint32_t& r3, uint32_t addr)
{
    asm volatile("ldmatrix.sync.aligned.m8n8.x4.shared.b16 {%0,%1,%2,%3}, [%4];"
                 : "=r"(r0), "=r"(r1), "=r"(r2), "=r"(r3) : "r"(addr));
}

__device__ __forceinline__ uint32_t smem_u32(const void* p)
{
    uint32_t a;
    asm("{ .reg .u64 t; cvta.to.shared.u64 t, %1; cvt.u32.u64 %0, t; }"
        : "=r"(a) : "l"(p));
    return a;
}

__device__ __forceinline__ float exp2_poly(float t)
{
    t = fmaxf(t, -125.f);
    float ft = floorf(t);
    float f = t - ft;
    float p = 1.5403530e-4f;
    p = fmaf(p, f, 1.3333558e-3f);
    p = fmaf(p, f, 9.6181291e-3f);
    p = fmaf(p, f, 5.5504109e-2f);
    p = fmaf(p, f, 2.4022651e-1f);
    p = fmaf(p, f, 6.9314718e-1f);
    p = fmaf(p, f, 1.0f);
    return __int_as_float(__float_as_int(p) + (((int)ft) << 23));
}

__device__ __forceinline__ uint32_t pack_bf16x2(float odd, float even)
{
    uint32_t d;
    asm("cvt.rn.bf16x2.f32 %0, %1, %2;" : "=r"(d) : "f"(odd), "f"(even));
    return d;
}

__device__ __forceinline__ void decode_row(int row, int& h, int& tc, int& r, int& off)
{
    if (row < 32768)      { h = row >> 13;                tc = row & 8191; r = 1; off = 0; }
    else if (row < 49152) { int u = row - 32768; h = 4 + (u >> 12); tc = u & 4095; r = 2; off = 1; }
    else                  { int u = row - 49152; h = 8 + (u >> 11); tc = u & 2047; r = 4; off = 2; }
}

// ---------------------------------------------------------------------------
// wgemm: split-bf16 HMMA GEMM, C = A @ B^T + bias.
// 512 threads / 16 warps (4 warps/SMSP), warp tile 64x16 — doubles
// latency-hiding streams for the tensor pipe; same 128x128 CTA tile.
// ---------------------------------------------------------------------------
#define TILE_B 10240
#define STG_B  40960

template <int MODE>
__global__ __launch_bounds__(512) void wgemm(const float* __restrict__ bias,
                                             float* __restrict__ Cout)
{
    constexpr int NTOT = (MODE == 0) ? E3 : EDIM;
    constexpr int NC = 24;
    extern __shared__ char smem[];

    const int tid = threadIdx.x;
    const int lane = tid & 31;
    const int wid = tid >> 5;
    const int rowBase = blockIdx.y << 7;
    const int colBase = blockIdx.x << 7;
    const int mBase = (wid & 1) * 64;      // 2 m-tiles of 64
    const int nBase = (wid >> 1) * 16;     // 8 n-tiles of 16

    const __nv_bfloat16* Ahi = (MODE == 0) ? g_xhi : g_onhi;
    const __nv_bfloat16* Alo = (MODE == 0) ? g_xlo : g_onlo;
    const __nv_bfloat16* Bhi = (MODE == 0) ? g_wqhi : g_wohi;
    const __nv_bfloat16* Blo = (MODE == 0) ? g_wqlo : g_wolo;
    float* C = (MODE == 0) ? g_qkv : Cout;

    // global loads: 512 threads, thread -> (row = tid>>2, 8-elem quarter = tid&3)
    const int lr = tid >> 2;
    const int lq = tid & 3;
    const __nv_bfloat16* gA0 = Ahi + (size_t)(rowBase + lr) * EDIM + lq * 8;
    const __nv_bfloat16* gA1 = Alo + (size_t)(rowBase + lr) * EDIM + lq * 8;
    const __nv_bfloat16* gB0 = Bhi + (size_t)(colBase + lr) * EDIM + lq * 8;
    const __nv_bfloat16* gB1 = Blo + (size_t)(colBase + lr) * EDIM + lq * 8;
    const uint32_t soff = (uint32_t)(lr * 80 + lq * 16);

    const uint32_t smbase = smem_u32(smem);
    const int laneR = lane & 15;
    const int laneH = (lane >> 4) * 16;

    float acc[4][2][4];
#pragma unroll
    for (int mi = 0; mi < 4; ++mi)
#pragma unroll
        for (int ni = 0; ni < 2; ++ni)
#pragma unroll
            for (int r = 0; r < 4; ++r) acc[mi][ni][r] = 0.f;

    {
        char* st = smem;
        *(uint4*)(st + 0 * TILE_B + soff) = *(const uint4*)(gA0);
        *(uint4*)(st + 1 * TILE_B + soff) = *(const uint4*)(gA1);
        *(uint4*)(st + 2 * TILE_B + soff) = *(const uint4*)(gB0);
        *(uint4*)(st + 3 * TILE_B + soff) = *(const uint4*)(gB1);
    }
    __syncthreads();

    const int g = lane >> 2;
    const int q = lane & 3;

    for (int c = 0; c < NC; ++c) {
        const int stg = c & 1;
        uint4 ra[4];
        if (c + 1 < NC) {
            const int off = (c + 1) * 32;
            ra[0] = *(const uint4*)(gA0 + off);
            ra[1] = *(const uint4*)(gA1 + off);
            ra[2] = *(const uint4*)(gB0 + off);
            ra[3] = *(const uint4*)(gB1 + off);
        }

        const uint32_t As = smbase + stg * STG_B;
#pragma unroll
        for (int k0 = 0; k0 < 32; k0 += 16) {
            uint32_t ahi[4][4], alo[4][4];
#pragma unroll
            for (int mi = 0; mi < 4; ++mi) {
                const uint32_t ad = As + (uint32_t)((mBase + mi * 16 + laneR) * 80
                                                    + k0 * 2 + laneH);
                ldmx4(ahi[mi][0], ahi[mi][1], ahi[mi][2], ahi[mi][3], ad);
                ldmx4(alo[mi][0], alo[mi][1], alo[mi][2], alo[mi][3], ad + TILE_B);
            }
            uint32_t bhi[2][2], blo[2][2];
            {
                const uint32_t bd = As + 2 * TILE_B
                                  + (uint32_t)((nBase + laneR) * 80 + k0 * 2 + laneH);
                uint32_t r0, r1, r2, r3;
                ldmx4(r0, r1, r2, r3, bd);
                bhi[0][0] = r0; bhi[0][1] = r2;
                bhi[1][0] = r1; bhi[1][1] = r3;
                ldmx4(r0, r1, r2, r3, bd + TILE_B);
                blo[0][0] = r0; blo[0][1] = r2;
                blo[1][0] = r1; blo[1][1] = r3;
            }
#pragma unroll
            for (int mi = 0; mi < 4; ++mi)
#pragma unroll
                for (int ni = 0; ni < 2; ++ni) {
                    mma16816(acc[mi][ni], ahi[mi], bhi[ni]);
                    mma16816(acc[mi][ni], ahi[mi], blo[ni]);
                    mma16816(acc[mi][ni], alo[mi], bhi[ni]);
                }
        }

        if (c + 1 < NC) {
            char* st = smem + ((c + 1) & 1) * STG_B;
            *(uint4*)(st + 0 * TILE_B + soff) = ra[0];
            *(uint4*)(st + 1 * TILE_B + soff) = ra[1];
            *(uint4*)(st + 2 * TILE_B + soff) = ra[2];
            *(uint4*)(st + 3 * TILE_B + soff) = ra[3];
        }
        __syncthreads();
    }

#pragma unroll
    for (int mi = 0; mi < 4; ++mi) {
        const int row0 = rowBase + mBase + mi * 16 + g;
#pragma unroll
        for (int ni = 0; ni < 2; ++ni) {
            const int colg = colBase + nBase + ni * 8 + q * 2;
            const float b0 = bias[colg], b1 = bias[colg + 1];
            float* c0 = C + (size_t)row0 * NTOT + colg;
            float* c1 = C + (size_t)(row0 + 8) * NTOT + colg;
            c0[0] = acc[mi][ni][0] + b0; c0[1] = acc[mi][ni][1] + b1;
            c1[0] = acc[mi][ni][2] + b0; c1[1] = acc[mi][ni][3] + b1;
        }
    }
}

// ---------------------------------------------------------------------------
template <int WHICH>
__global__ void split_k(const float* __restrict__ src)
{
    __nv_bfloat16* hi = (WHICH == 0) ? g_xhi : (WHICH == 1) ? g_wqhi : g_wohi;
    __nv_bfloat16* lo = (WHICH == 0) ? g_xlo : (WHICH == 1) ? g_wqlo : g_wolo;
    const int i = blockIdx.x * blockDim.x + threadIdx.x;
    float4 v = ((const float4*)src)[i];
    float a[4] = {v.x, v.y, v.z, v.w};
    const int base = i * 4;
#pragma unroll
    for (int j = 0; j < 4; ++j) {
        __nv_bfloat16 h = __float2bfloat16_rn(a[j]);
        hi[base + j] = h;
        lo[base + j] = __float2bfloat16_rn(a[j] - __bfloat162float(h));
    }
}

// qkv fp32 -> compact split-bf16 Q/K
__global__ void conv_qk()
{
    const int idx = blockIdx.x * 256 + threadIdx.x;
    const int row = idx >> 4;
    const int j = (idx & 15) * 4;
    int h, tc, r, off;
    decode_row(row, h, tc, r, off);
    const int tok = off + tc * r;
    const float4 qv = *(const float4*)(g_qkv + (size_t)tok * E3 + h * HD + j);
    const float4 kv = *(const float4*)(g_qkv + (size_t)tok * E3 + EDIM + h * HD + j);
    float qa[4] = {qv.x, qv.y, qv.z, qv.w};
    float ka[4] = {kv.x, kv.y, kv.z, kv.w};
    __nv_bfloat16 qh[4], ql[4], kh[4], kl[4];
#pragma unroll
    for (int t = 0; t < 4; ++t) {
        qh[t] = __float2bfloat16_rn(qa[t]);
        ql[t] = __float2bfloat16_rn(qa[t] - __bfloat162float(qh[t]));
        kh[t] = __float2bfloat16_rn(ka[t]);
        kl[t] = __float2bfloat16_rn(ka[t] - __bfloat162float(kh[t]));
    }
    const size_t o = (size_t)row * HD + j;
    *(uint2*)(g_qchi + o) = *(uint2*)qh;
    *(uint2*)(g_qclo + o) = *(uint2*)ql;
    *(uint2*)(g_kchi + o) = *(uint2*)kh;
    *(uint2*)(g_kclo + o) = *(uint2*)kl;
}

// qkv fp32 V -> compact transposed split-bf16 Vt [head][d][tokc]
__global__ __launch_bounds__(256) void conv_v()
{
    __shared__ float vs[64][65];
    const int tid = threadIdx.x;
    const int row64 = blockIdx.x * 64;
    int h, tc0, r, off;
    decode_row(row64, h, tc0, r, off);
    const int ntokc = (h < 4) ? 8192 : (h < 8) ? 4096 : 2048;
    const int hoff = (h < 4) ? h * 8192 : (h < 8) ? 32768 + (h - 4) * 4096
                                                  : 49152 + (h - 8) * 2048;
    {
        const int tr = tid >> 2;
        const int j = (tid & 3) * 16;
        const int tok = off + (tc0 + tr) * r;
        const float* vp = g_qkv + (size_t)tok * E3 + 2 * EDIM + h * HD + j;
#pragma unroll
        for (int i = 0; i < 4; ++i) {
            float4 v = *(const float4*)(vp + i * 4);
            vs[tr][j + i * 4 + 0] = v.x; vs[tr][j + i * 4 + 1] = v.y;
            vs[tr][j + i * 4 + 2] = v.z; vs[tr][j + i * 4 + 3] = v.w;
        }
    }
    __syncthreads();
    const int d = tid >> 2;
    const int k0 = (tid & 3) * 16;
    __nv_bfloat16 vh[16], vl[16];
#pragma unroll
    for (int i = 0; i < 16; ++i) {
        float v = vs[k0 + i][d];
        vh[i] = __float2bfloat16_rn(v);
        vl[i] = __float2bfloat16_rn(v - __bfloat162float(vh[i]));
    }
    const size_t o = (size_t)hoff * HD + (size_t)d * ntokc + tc0 + k0;
    *(uint4*)(g_vthi + o)     = *(uint4*)vh;
    *(uint4*)(g_vthi + o + 8) = *(uint4*)(vh + 8);
    *(uint4*)(g_vtlo + o)     = *(uint4*)vl;
    *(uint4*)(g_vtlo + o + 8) = *(uint4*)(vl + 8);
}

// ---------------------------------------------------------------------------
// Tensor-core flash attention on compact layouts (unchanged from R9 pass).
// ---------------------------------------------------------------------------
#define AP 144
#define AKHI 0
#define AKLO 9216
#define AVHI 18432
#define AVLO 27648
#define ASTG 36864

__global__ __launch_bounds__(256, 1) void attn_tc()
{
    extern __shared__ char sm[];
    const int tid = threadIdx.x;
    const int lane = tid & 31;
    const int w = tid >> 5;
    const int g = lane >> 2;
    const int q = lane & 3;

    const int p = blockIdx.y;
    int mseg, hh, grp;
    if (p < 16)      { grp = 0; mseg = p >> 2;        hh = p & 3; }
    else if (p < 24) { grp = 1; mseg = (p - 16) >> 2; hh = (p - 16) & 3; }
    else             { grp = 2; mseg = 0;             hh = p - 24; }
    const int h = grp * 4 + hh;
    const int r = 1 << grp;
    const int off = grp;
    const int ntokc = 8192 >> grp;
    const int hoff = (grp == 0) ? h * 8192 : (grp == 1) ? 32768 + hh * 4096
                                                        : 49152 + hh * 2048;
    const int csegrel = mseg * 2048;
    const int cseg = hoff + csegrel;

    {
        const int row = tid >> 1, hf = tid & 1;
        const size_t go = (size_t)(cseg + blockIdx.x * 128 + row) * HD + hf * 32;
        uint4 a0 = *(const uint4*)(g_qchi + go);
        uint4 a1 = *(const uint4*)(g_qchi + go + 8);
        uint4 a2 = *(const uint4*)(g_qchi + go + 16);
        uint4 a3 = *(const uint4*)(g_qchi + go + 24);
        uint4 b0 = *(const uint4*)(g_qclo + go);
        uint4 b1 = *(const uint4*)(g_qclo + go + 8);
        uint4 b2 = *(const uint4*)(g_qclo + go + 16);
        uint4 b3 = *(const uint4*)(g_qclo + go + 24);
        char* d0 = sm + row * AP + hf * 64;
        char* d1 = sm + ASTG + row * AP + hf * 64;
        *(uint4*)d0        = a0; *(uint4*)(d0 + 16) = a1;
        *(uint4*)(d0 + 32) = a2; *(uint4*)(d0 + 48) = a3;
        *(uint4*)d1        = b0; *(uint4*)(d1 + 16) = b1;
        *(uint4*)(d1 + 32) = b2; *(uint4*)(d1 + 48) = b3;
    }
    __syncthreads();
    uint32_t qhf[4][4], qlf[4][4];
#pragma unroll
    for (int kst = 0; kst < 4; ++kst)
#pragma unroll
        for (int rr = 0; rr < 4; ++rr) {
            const int row = w * 16 + g + 8 * (rr & 1);
            const int col = kst * 16 + q * 2 + 8 * (rr >> 1);
            qhf[kst][rr] = *(const uint32_t*)(sm + row * AP + col * 2);
            qlf[kst][rr] = *(const uint32_t*)(sm + ASTG + row * AP + col * 2);
        }
    __syncthreads();

    const int trow = tid >> 2, tq = tid & 3;
    const __nv_bfloat16* kh = g_kchi + (size_t)(cseg + trow) * HD + tq * 16;
    const __nv_bfloat16* kl = g_kclo + (size_t)(cseg + trow) * HD + tq * 16;
    const size_t vbase = (size_t)hoff * HD + (size_t)trow * ntokc + csegrel + tq * 16;
    const __nv_bfloat16* vh = g_vthi + vbase;
    const __nv_bfloat16* vl = g_vtlo + vbase;
    const uint32_t ts = trow * AP + tq * 32;

    {
        char* st = sm;
        *(uint4*)(st + AKHI + ts)      = *(const uint4*)(kh);
        *(uint4*)(st + AKHI + ts + 16) = *(const uint4*)(kh + 8);
        *(uint4*)(st + AKLO + ts)      = *(const uint4*)(kl);
        *(uint4*)(st + AKLO + ts + 16) = *(const uint4*)(kl + 8);
        *(uint4*)(st + AVHI + ts)      = *(const uint4*)(vh);
        *(uint4*)(st + AVHI + ts + 16) = *(const uint4*)(vh + 8);
        *(uint4*)(st + AVLO + ts)      = *(const uint4*)(vl);
        *(uint4*)(st + AVLO + ts + 16) = *(const uint4*)(vl + 8);
    }
    __syncthreads();

    float oacc[8][4];
#pragma unroll
    for (int nd = 0; nd < 8; ++nd)
#pragma unroll
        for (int c = 0; c < 4; ++c) oacc[nd][c] = 0.f;
    float m0 = -CUDART_INF_F, m1 = -CUDART_INF_F, l0 = 0.f, l1 = 0.f;

    for (int kt = 0; kt < 32; ++kt) {
        const char* st = sm + (kt & 1) * ASTG;

        uint4 ra[8];
        if (kt < 31) {
            const int ko = (kt + 1) * 64;
            const size_t kof = (size_t)ko * HD;
            ra[0] = *(const uint4*)(kh + kof); ra[1] = *(const uint4*)(kh + kof + 8);
            ra[2] = *(const uint4*)(kl + kof); ra[3] = *(const uint4*)(kl + kof + 8);
            ra[4] = *(const uint4*)(vh + ko);  ra[5] = *(const uint4*)(vh + ko + 8);
            ra[6] = *(const uint4*)(vl + ko);  ra[7] = *(const uint4*)(vl + ko + 8);
        }

        float sacc[8][4];
#pragma unroll
        for (int t = 0; t < 8; ++t)
#pragma unroll
            for (int c = 0; c < 4; ++c) sacc[t][c] = 0.f;
#pragma unroll
        for (int kst = 0; kst < 4; ++kst)
#pragma unroll
            for (int ni = 0; ni < 8; ++ni) {
                const char* kb = st + AKHI + (ni * 8 + g) * AP + kst * 32 + q * 4;
                const char* lb = st + AKLO + (ni * 8 + g) * AP + kst * 32 + q * 4;
                uint32_t bh[2] = {*(const uint32_t*)kb, *(const uint32_t*)(kb + 16)};
                uint32_t bl[2] = {*(const uint32_t*)lb, *(const uint32_t*)(lb + 16)};
                mma16816(sacc[ni], qhf[kst], bh);
                mma16816(sacc[ni], qhf[kst], bl);
                mma16816(sacc[ni], qlf[kst], bh);
            }

        float rm0 = -CUDART_INF_F, rm1 = -CUDART_INF_F;
#pragma unroll
        for (int t = 0; t < 8; ++t) {
#pragma unroll
            for (int c = 0; c < 4; ++c) sacc[t][c] *= CSC;
            rm0 = fmaxf(rm0, fmaxf(sacc[t][0], sacc[t][1]));
            rm1 = fmaxf(rm1, fmaxf(sacc[t][2], sacc[t][3]));
        }
        rm0 = fmaxf(rm0, __shfl_xor_sync(0xffffffffu, rm0, 1));
        rm0 = fmaxf(rm0, __shfl_xor_sync(0xffffffffu, rm0, 2));
        rm1 = fmaxf(rm1, __shfl_xor_sync(0xffffffffu, rm1, 1));
        rm1 = fmaxf(rm1, __shfl_xor_sync(0xffffffffu, rm1, 2));
        const float mn0 = fmaxf(m0, rm0), mn1 = fmaxf(m1, rm1);
        const float cr0 = exp2_poly(m0 - mn0), cr1 = exp2_poly(m1 - mn1);
        m0 = mn0; m1 = mn1;

        float rs0 = 0.f, rs1 = 0.f;
#pragma unroll
        for (int t = 0; t < 8; ++t) {
            sacc[t][0] = exp2_poly(sacc[t][0] - mn0); rs0 += sacc[t][0];
            sacc[t][1] = exp2_poly(sacc[t][1] - mn0); rs0 += sacc[t][1];
            sacc[t][2] = exp2_poly(sacc[t][2] - mn1); rs1 += sacc[t][2];
            sacc[t][3] = exp2_poly(sacc[t][3] - mn1); rs1 += sacc[t][3];
        }
        rs0 += __shfl_xor_sync(0xffffffffu, rs0, 1);
        rs0 += __shfl_xor_sync(0xffffffffu, rs0, 2);
        rs1 += __shfl_xor_sync(0xffffffffu, rs1, 1);
        rs1 += __shfl_xor_sync(0xffffffffu, rs1, 2);
        l0 = l0 * cr0 + rs0;
        l1 = l1 * cr1 + rs1;
#pragma unroll
        for (int nd = 0; nd < 8; ++nd) {
            oacc[nd][0] *= cr0; oacc[nd][1] *= cr0;
            oacc[nd][2] *= cr1; oacc[nd][3] *= cr1;
        }

#pragma unroll
        for (int kb = 0; kb < 4; ++kb) {
            uint32_t ah[4], al[4];
#pragma unroll
            for (int half = 0; half < 2; ++half) {
                const float* s0 = sacc[2 * kb + half];
                ah[2 * half]     = pack_bf16x2(s0[1], s0[0]);
                ah[2 * half + 1] = pack_bf16x2(s0[3], s0[2]);
                const float e0 = s0[0] - __uint_as_float(ah[2 * half] << 16);
                const float e1 = s0[1] - __uint_as_float(ah[2 * half] & 0xFFFF0000u);
                const float e2 = s0[2] - __uint_as_float(ah[2 * half + 1] << 16);
                const float e3 = s0[3] - __uint_as_float(ah[2 * half + 1] & 0xFFFF0000u);
                al[2 * half]     = pack_bf16x2(e1, e0);
                al[2 * half + 1] = pack_bf16x2(e3, e2);
            }
#pragma unroll
            for (int nd = 0; nd < 8; ++nd) {
                const char* vb = st + AVHI + (nd * 8 + g) * AP + kb * 32 + q * 4;
                const char* wb = st + AVLO + (nd * 8 + g) * AP + kb * 32 + q * 4;
                uint32_t bh[2] = {*(const uint32_t*)vb, *(const uint32_t*)(vb + 16)};
                uint32_t bl[2] = {*(const uint32_t*)wb, *(const uint32_t*)(wb + 16)};
                mma16816(oacc[nd], ah, bh);
                mma16816(oacc[nd], al, bh);
                mma16816(oacc[nd], ah, bl);
            }
        }

        if (kt < 31) {
            char* dst = sm + ((kt + 1) & 1) * ASTG;
            *(uint4*)(dst + AKHI + ts)      = ra[0];
            *(uint4*)(dst + AKHI + ts + 16) = ra[1];
            *(uint4*)(dst + AKLO + ts)      = ra[2];
            *(uint4*)(dst + AKLO + ts + 16) = ra[3];
            *(uint4*)(dst + AVHI + ts)      = ra[4];
            *(uint4*)(dst + AVHI + ts + 16) = ra[5];
            *(uint4*)(dst + AVLO + ts)      = ra[6];
            *(uint4*)(dst + AVLO + ts + 16) = ra[7];
        }
        __syncthreads();
    }

    const float inv0 = 1.f / l0, inv1 = 1.f / l1;
    const int ci0 = csegrel + blockIdx.x * 128 + w * 16 + g;
    const int tok0 = off + ci0 * r;
    const int tok1 = off + (ci0 + 8) * r;
    float* o0 = g_o + (size_t)tok0 * EDIM + h * HD + q * 2;
    float* o1 = g_o + (size_t)tok1 * EDIM + h * HD + q * 2;
#pragma unroll
    for (int nd = 0; nd < 8; ++nd) {
        *(float2*)(o0 + nd * 8) = make_float2(oacc[nd][0] * inv0, oacc[nd][1] * inv0);
        *(float2*)(o1 + nd * 8) = make_float2(oacc[nd][2] * inv1, oacc[nd][3] * inv1);
    }
}

// ---------------------------------------------------------------------------
__global__ __launch_bounds__(256) void layernorm_k(
    const float* __restrict__ gamma, const float* __restrict__ beta)
{
    __shared__ float red[8];
    __shared__ float bcast;
    const int row = blockIdx.x;
    const int tid = threadIdx.x;
    const int lane = tid & 31, wid = tid >> 5;
    const float* x = g_o + (size_t)row * EDIM;
    float v0 = x[tid], v1 = x[tid + 256], v2 = x[tid + 512];

    float ssum = v0 + v1 + v2;
#pragma unroll
    for (int w = 16; w >= 1; w >>= 1) ssum += __shfl_xor_sync(0xffffffffu, ssum, w);
    if (lane == 0) red[wid] = ssum;
    __syncthreads();
    if (tid < 32) {
        float t = (tid < 8) ? red[tid] : 0.f;
#pragma unroll
        for (int w = 4; w >= 1; w >>= 1) t += __shfl_xor_sync(0xffffffffu, t, w);
        if (tid == 0) bcast = t;
    }
    __syncthreads();
    const float mu = bcast * (1.f / 768.f);
    float d0 = v0 - mu, d1 = v1 - mu, d2 = v2 - mu;
    float sq = d0 * d0 + d1 * d1 + d2 * d2;
#pragma unroll
    for (int w = 16; w >= 1; w >>= 1) sq += __shfl_xor_sync(0xffffffffu, sq, w);
    __syncthreads();
    if (lane == 0) red[wid] = sq;
    __syncthreads();
    if (tid < 32) {
        float t = (tid < 8) ? red[tid] : 0.f;
#pragma unroll
        for (int w = 4; w >= 1; w >>= 1) t += __shfl_xor_sync(0xffffffffu, t, w);
        if (tid == 0) bcast = t;
    }
    __syncthreads();
    const float rstd = rsqrtf(bcast * (1.f / 768.f) + 1e-5f);
    const size_t rb = (size_t)row * EDIM;
#pragma unroll
    for (int part = 0; part < 3; ++part) {
        const int idx = tid + part * 256;
        const float d = (part == 0) ? d0 : (part == 1) ? d1 : d2;
        const float y = d * rstd * gamma[idx] + beta[idx];
        __nv_bfloat16 h = __float2bfloat16_rn(y);
        g_onhi[rb + idx] = h;
        g_onlo[rb + idx] = __float2bfloat16_rn(y - __bfloat162float(h));
    }
}

__global__ void zero_o() {
    ((float4*)g_o)[blockIdx.x * blockDim.x + threadIdx.x] =
        make_float4(0.f, 0.f, 0.f, 0.f);
}

// ---------------------------------------------------------------------------
extern "C" void kernel_launch(void* const* d_in, const int* in_sizes, int n_in,
                              void* d_out, int out_size)
{
    const float* x      = (const float*)d_in[0];
    const float* w_qkv  = (const float*)d_in[1];
    const float* b_qkv  = (const float*)d_in[2];
    const float* w_out  = (const float*)d_in[3];
    const float* b_out  = (const float*)d_in[4];
    const float* ln_g   = (const float*)d_in[5];
    const float* ln_b   = (const float*)d_in[6];
    float* out = (float*)d_out;

    const int SMEM_GEMM = 2 * STG_B;      // 80 KB
    const int SMEM_ATTN = 2 * ASTG;       // 72 KB
    cudaFuncSetAttribute(wgemm<0>, cudaFuncAttributeMaxDynamicSharedMemorySize, SMEM_GEMM);
    cudaFuncSetAttribute(wgemm<1>, cudaFuncAttributeMaxDynamicSharedMemorySize, SMEM_GEMM);
    cudaFuncSetAttribute(attn_tc, cudaFuncAttributeMaxDynamicSharedMemorySize, SMEM_ATTN);

    split_k<0><<<(NTOK * EDIM / 4) / 256, 256>>>(x);
    split_k<1><<<(E3 * EDIM / 4) / 256, 256>>>(w_qkv);
    split_k<2><<<(EDIM * EDIM / 4) / 256, 256>>>(w_out);

    dim3 g1(E3 / 128, NTOK / 128);
    wgemm<0><<<g1, 512, SMEM_GEMM>>>(b_qkv, nullptr);

    conv_qk<<<(NCROWS * 16) / 256, 256>>>();
    conv_v<<<NCROWS / 64, 256>>>();
    zero_o<<<(NTOK * EDIM / 4) / 256, 256>>>();

    dim3 g2(16, 28);
    attn_tc<<<g2, 256, SMEM_ATTN>>>();

    layernorm_k<<<NTOK, 256>>>(ln_g, ln_b);

    dim3 g3(EDIM / 128, NTOK / 128);
    wgemm<1><<<g3, 512, SMEM_GEMM>>>(b_out, out);
}

// round 16
// speedup vs baseline: 1.9898x; 1.0234x over previous
#include <cuda_runtime.h>
#include <cuda_fp16.h>
#include <math_constants.h>
#include <cstdint>

#define NTOK 8192
#define EDIM 768
#define E3   2304
#define HD   64
#define CSC  0.18033688011112042f   // 0.125 * log2(e)
#define NCROWS 57344                // 4*8192 + 4*4096 + 4*2048

__device__ float g_qkv[NTOK * E3];
__device__ float g_o[NTOK * EDIM];
__device__ __half g_xhi[NTOK * EDIM];
__device__ __half g_xlo[NTOK * EDIM];
__device__ __half g_wqhi[E3 * EDIM];
__device__ __half g_wqlo[E3 * EDIM];
__device__ __half g_wohi[EDIM * EDIM];
__device__ __half g_wolo[EDIM * EDIM];
__device__ __half g_onhi[NTOK * EDIM];
__device__ __half g_onlo[NTOK * EDIM];
__device__ __half g_qchi[NCROWS * HD];
__device__ __half g_qclo[NCROWS * HD];
__device__ __half g_kchi[NCROWS * HD];
__device__ __half g_kclo[NCROWS * HD];
__device__ __half g_vthi[NCROWS * HD];  // [head][d][tokc]
__device__ __half g_vtlo[NCROWS * HD];

__device__ __forceinline__ void mma16816(float* c, const uint32_t* a, const uint32_t* b)
{
    asm volatile(
        "mma.sync.aligned.m16n8k16.row.col.f32.f16.f16.f32 "
        "{%0,%1,%2,%3}, {%4,%5,%6,%7}, {%8,%9}, {%0,%1,%2,%3};"
        : "+f"(c[0]), "+f"(c[1]), "+f"(c[2]), "+f"(c[3])
        : "r"(a[0]), "r"(a[1]), "r"(a[2]), "r"(a[3]), "r"(b[0]), "r"(b[1]));
}

__device__ __forceinline__ void ldmx4(uint32_t& r0, uint32_t& r1, uint32_t& r2,
                                      uint32_t& r3, uint32_t addr)
{
    asm volatile("ldmatrix.sync.aligned.m8n8.x4.shared.b16 {%0,%1,%2,%3}, [%4];"
                 : "=r"(r0), "=r"(r1), "=r"(r2), "=r"(r3) : "r"(addr));
}

__device__ __forceinline__ uint32_t smem_u32(const void* p)
{
    uint32_t a;
    asm("{ .reg .u64 t; cvta.to.shared.u64 t, %1; cvt.u32.u64 %0, t; }"
        : "=r"(a) : "l"(p));
    return a;
}

__device__ __forceinline__ float exp2_poly(float t)
{
    t = fmaxf(t, -125.f);
    float ft = floorf(t);
    float f = t - ft;
    float p = 1.5403530e-4f;
    p = fmaf(p, f, 1.3333558e-3f);
    p = fmaf(p, f, 9.6181291e-3f);
    p = fmaf(p, f, 5.5504109e-2f);
    p = fmaf(p, f, 2.4022651e-1f);
    p = fmaf(p, f, 6.9314718e-1f);
    p = fmaf(p, f, 1.0f);
    return __int_as_float(__float_as_int(p) + (((int)ft) << 23));
}

// pack two fp32 -> f16x2 register; 'even' goes to low half, 'odd' to high
__device__ __forceinline__ uint32_t pack_f16x2(float odd, float even)
{
    __half2 h = __floats2half2_rn(even, odd);
    return *(uint32_t*)&h;
}

__device__ __forceinline__ void decode_row(int row, int& h, int& tc, int& r, int& off)
{
    if (row < 32768)      { h = row >> 13;                tc = row & 8191; r = 1; off = 0; }
    else if (row < 49152) { int u = row - 32768; h = 4 + (u >> 12); tc = u & 4095; r = 2; off = 1; }
    else                  { int u = row - 49152; h = 8 + (u >> 11); tc = u & 2047; r = 4; off = 2; }
}

// ---------------------------------------------------------------------------
// wgemm: split-fp16 HMMA GEMM, C = A @ B^T + bias.
// 512 threads / 16 warps, warp tile 64x16, 128x128 CTA tile, 2-stage smem.
// ---------------------------------------------------------------------------
#define TILE_B 10240
#define STG_B  40960

template <int MODE>
__global__ __launch_bounds__(512) void wgemm(const float* __restrict__ bias,
                                             float* __restrict__ Cout)
{
    constexpr int NTOT = (MODE == 0) ? E3 : EDIM;
    constexpr int NC = 24;
    extern __shared__ char smem[];

    const int tid = threadIdx.x;
    const int lane = tid & 31;
    const int wid = tid >> 5;
    const int rowBase = blockIdx.y << 7;
    const int colBase = blockIdx.x << 7;
    const int mBase = (wid & 1) * 64;
    const int nBase = (wid >> 1) * 16;

    const __half* Ahi = (MODE == 0) ? g_xhi : g_onhi;
    const __half* Alo = (MODE == 0) ? g_xlo : g_onlo;
    const __half* Bhi = (MODE == 0) ? g_wqhi : g_wohi;
    const __half* Blo = (MODE == 0) ? g_wqlo : g_wolo;
    float* C = (MODE == 0) ? g_qkv : Cout;

    const int lr = tid >> 2;
    const int lq = tid & 3;
    const __half* gA0 = Ahi + (size_t)(rowBase + lr) * EDIM + lq * 8;
    const __half* gA1 = Alo + (size_t)(rowBase + lr) * EDIM + lq * 8;
    const __half* gB0 = Bhi + (size_t)(colBase + lr) * EDIM + lq * 8;
    const __half* gB1 = Blo + (size_t)(colBase + lr) * EDIM + lq * 8;
    const uint32_t soff = (uint32_t)(lr * 80 + lq * 16);

    const uint32_t smbase = smem_u32(smem);
    const int laneR = lane & 15;
    const int laneH = (lane >> 4) * 16;

    float acc[4][2][4];
#pragma unroll
    for (int mi = 0; mi < 4; ++mi)
#pragma unroll
        for (int ni = 0; ni < 2; ++ni)
#pragma unroll
            for (int r = 0; r < 4; ++r) acc[mi][ni][r] = 0.f;

    {
        char* st = smem;
        *(uint4*)(st + 0 * TILE_B + soff) = *(const uint4*)(gA0);
        *(uint4*)(st + 1 * TILE_B + soff) = *(const uint4*)(gA1);
        *(uint4*)(st + 2 * TILE_B + soff) = *(const uint4*)(gB0);
        *(uint4*)(st + 3 * TILE_B + soff) = *(const uint4*)(gB1);
    }
    __syncthreads();

    const int g = lane >> 2;
    const int q = lane & 3;

    for (int c = 0; c < NC; ++c) {
        const int stg = c & 1;
        uint4 ra[4];
        if (c + 1 < NC) {
            const int off = (c + 1) * 32;
            ra[0] = *(const uint4*)(gA0 + off);
            ra[1] = *(const uint4*)(gA1 + off);
            ra[2] = *(const uint4*)(gB0 + off);
            ra[3] = *(const uint4*)(gB1 + off);
        }

        const uint32_t As = smbase + stg * STG_B;
#pragma unroll
        for (int k0 = 0; k0 < 32; k0 += 16) {
            uint32_t ahi[4][4], alo[4][4];
#pragma unroll
            for (int mi = 0; mi < 4; ++mi) {
                const uint32_t ad = As + (uint32_t)((mBase + mi * 16 + laneR) * 80
                                                    + k0 * 2 + laneH);
                ldmx4(ahi[mi][0], ahi[mi][1], ahi[mi][2], ahi[mi][3], ad);
                ldmx4(alo[mi][0], alo[mi][1], alo[mi][2], alo[mi][3], ad + TILE_B);
            }
            uint32_t bhi[2][2], blo[2][2];
            {
                const uint32_t bd = As + 2 * TILE_B
                                  + (uint32_t)((nBase + laneR) * 80 + k0 * 2 + laneH);
                uint32_t r0, r1, r2, r3;
                ldmx4(r0, r1, r2, r3, bd);
                bhi[0][0] = r0; bhi[0][1] = r2;
                bhi[1][0] = r1; bhi[1][1] = r3;
                ldmx4(r0, r1, r2, r3, bd + TILE_B);
                blo[0][0] = r0; blo[0][1] = r2;
                blo[1][0] = r1; blo[1][1] = r3;
            }
#pragma unroll
            for (int mi = 0; mi < 4; ++mi)
#pragma unroll
                for (int ni = 0; ni < 2; ++ni) {
                    mma16816(acc[mi][ni], ahi[mi], bhi[ni]);
                    mma16816(acc[mi][ni], ahi[mi], blo[ni]);
                    mma16816(acc[mi][ni], alo[mi], bhi[ni]);
                }
        }

        if (c + 1 < NC) {
            char* st = smem + ((c + 1) & 1) * STG_B;
            *(uint4*)(st + 0 * TILE_B + soff) = ra[0];
            *(uint4*)(st + 1 * TILE_B + soff) = ra[1];
            *(uint4*)(st + 2 * TILE_B + soff) = ra[2];
            *(uint4*)(st + 3 * TILE_B + soff) = ra[3];
        }
        __syncthreads();
    }

#pragma unroll
    for (int mi = 0; mi < 4; ++mi) {
        const int row0 = rowBase + mBase + mi * 16 + g;
#pragma unroll
        for (int ni = 0; ni < 2; ++ni) {
            const int colg = colBase + nBase + ni * 8 + q * 2;
            const float b0 = bias[colg], b1 = bias[colg + 1];
            float* c0 = C + (size_t)row0 * NTOT + colg;
            float* c1 = C + (size_t)(row0 + 8) * NTOT + colg;
            c0[0] = acc[mi][ni][0] + b0; c0[1] = acc[mi][ni][1] + b1;
            c1[0] = acc[mi][ni][2] + b0; c1[1] = acc[mi][ni][3] + b1;
        }
    }
}

// ---------------------------------------------------------------------------
template <int WHICH>
__global__ void split_k(const float* __restrict__ src)
{
    __half* hi = (WHICH == 0) ? g_xhi : (WHICH == 1) ? g_wqhi : g_wohi;
    __half* lo = (WHICH == 0) ? g_xlo : (WHICH == 1) ? g_wqlo : g_wolo;
    const int i = blockIdx.x * blockDim.x + threadIdx.x;
    float4 v = ((const float4*)src)[i];
    float a[4] = {v.x, v.y, v.z, v.w};
    const int base = i * 4;
#pragma unroll
    for (int j = 0; j < 4; ++j) {
        __half h = __float2half_rn(a[j]);
        hi[base + j] = h;
        lo[base + j] = __float2half_rn(a[j] - __half2float(h));
    }
}

// qkv fp32 -> compact split-fp16 Q/K
__global__ void conv_qk()
{
    const int idx = blockIdx.x * 256 + threadIdx.x;
    const int row = idx >> 4;
    const int j = (idx & 15) * 4;
    int h, tc, r, off;
    decode_row(row, h, tc, r, off);
    const int tok = off + tc * r;
    const float4 qv = *(const float4*)(g_qkv + (size_t)tok * E3 + h * HD + j);
    const float4 kv = *(const float4*)(g_qkv + (size_t)tok * E3 + EDIM + h * HD + j);
    float qa[4] = {qv.x, qv.y, qv.z, qv.w};
    float ka[4] = {kv.x, kv.y, kv.z, kv.w};
    __half qh[4], ql[4], kh[4], kl[4];
#pragma unroll
    for (int t = 0; t < 4; ++t) {
        qh[t] = __float2half_rn(qa[t]);
        ql[t] = __float2half_rn(qa[t] - __half2float(qh[t]));
        kh[t] = __float2half_rn(ka[t]);
        kl[t] = __float2half_rn(ka[t] - __half2float(kh[t]));
    }
    const size_t o = (size_t)row * HD + j;
    *(uint2*)(g_qchi + o) = *(uint2*)qh;
    *(uint2*)(g_qclo + o) = *(uint2*)ql;
    *(uint2*)(g_kchi + o) = *(uint2*)kh;
    *(uint2*)(g_kclo + o) = *(uint2*)kl;
}

// qkv fp32 V -> compact transposed split-fp16 Vt [head][d][tokc]
__global__ __launch_bounds__(256) void conv_v()
{
    __shared__ float vs[64][65];
    const int tid = threadIdx.x;
    const int row64 = blockIdx.x * 64;
    int h, tc0, r, off;
    decode_row(row64, h, tc0, r, off);
    const int ntokc = (h < 4) ? 8192 : (h < 8) ? 4096 : 2048;
    const int hoff = (h < 4) ? h * 8192 : (h < 8) ? 32768 + (h - 4) * 4096
                                                  : 49152 + (h - 8) * 2048;
    {
        const int tr = tid >> 2;
        const int j = (tid & 3) * 16;
        const int tok = off + (tc0 + tr) * r;
        const float* vp = g_qkv + (size_t)tok * E3 + 2 * EDIM + h * HD + j;
#pragma unroll
        for (int i = 0; i < 4; ++i) {
            float4 v = *(const float4*)(vp + i * 4);
            vs[tr][j + i * 4 + 0] = v.x; vs[tr][j + i * 4 + 1] = v.y;
            vs[tr][j + i * 4 + 2] = v.z; vs[tr][j + i * 4 + 3] = v.w;
        }
    }
    __syncthreads();
    const int d = tid >> 2;
    const int k0 = (tid & 3) * 16;
    __half vh[16], vl[16];
#pragma unroll
    for (int i = 0; i < 16; ++i) {
        float v = vs[k0 + i][d];
        vh[i] = __float2half_rn(v);
        vl[i] = __float2half_rn(v - __half2float(vh[i]));
    }
    const size_t o = (size_t)hoff * HD + (size_t)d * ntokc + tc0 + k0;
    *(uint4*)(g_vthi + o)     = *(uint4*)vh;
    *(uint4*)(g_vthi + o + 8) = *(uint4*)(vh + 8);
    *(uint4*)(g_vtlo + o)     = *(uint4*)vl;
    *(uint4*)(g_vtlo + o + 8) = *(uint4*)(vl + 8);
}

// ---------------------------------------------------------------------------
// Tensor-core flash attention on compact layouts (fp16 split operands).
// ---------------------------------------------------------------------------
#define AP 144
#define AKHI 0
#define AKLO 9216
#define AVHI 18432
#define AVLO 27648
#define ASTG 36864

__global__ __launch_bounds__(256, 1) void attn_tc()
{
    extern __shared__ char sm[];
    const int tid = threadIdx.x;
    const int lane = tid & 31;
    const int w = tid >> 5;
    const int g = lane >> 2;
    const int q = lane & 3;

    const int p = blockIdx.y;
    int mseg, hh, grp;
    if (p < 16)      { grp = 0; mseg = p >> 2;        hh = p & 3; }
    else if (p < 24) { grp = 1; mseg = (p - 16) >> 2; hh = (p - 16) & 3; }
    else             { grp = 2; mseg = 0;             hh = p - 24; }
    const int h = grp * 4 + hh;
    const int r = 1 << grp;
    const int off = grp;
    const int ntokc = 8192 >> grp;
    const int hoff = (grp == 0) ? h * 8192 : (grp == 1) ? 32768 + hh * 4096
                                                        : 49152 + hh * 2048;
    const int csegrel = mseg * 2048;
    const int cseg = hoff + csegrel;

    {
        const int row = tid >> 1, hf = tid & 1;
        const size_t go = (size_t)(cseg + blockIdx.x * 128 + row) * HD + hf * 32;
        uint4 a0 = *(const uint4*)(g_qchi + go);
        uint4 a1 = *(const uint4*)(g_qchi + go + 8);
        uint4 a2 = *(const uint4*)(g_qchi + go + 16);
        uint4 a3 = *(const uint4*)(g_qchi + go + 24);
        uint4 b0 = *(const uint4*)(g_qclo + go);
        uint4 b1 = *(const uint4*)(g_qclo + go + 8);
        uint4 b2 = *(const uint4*)(g_qclo + go + 16);
        uint4 b3 = *(const uint4*)(g_qclo + go + 24);
        char* d0 = sm + row * AP + hf * 64;
        char* d1 = sm + ASTG + row * AP + hf * 64;
        *(uint4*)d0        = a0; *(uint4*)(d0 + 16) = a1;
        *(uint4*)(d0 + 32) = a2; *(uint4*)(d0 + 48) = a3;
        *(uint4*)d1        = b0; *(uint4*)(d1 + 16) = b1;
        *(uint4*)(d1 + 32) = b2; *(uint4*)(d1 + 48) = b3;
    }
    __syncthreads();
    uint32_t qhf[4][4], qlf[4][4];
#pragma unroll
    for (int kst = 0; kst < 4; ++kst)
#pragma unroll
        for (int rr = 0; rr < 4; ++rr) {
            const int row = w * 16 + g + 8 * (rr & 1);
            const int col = kst * 16 + q * 2 + 8 * (rr >> 1);
            qhf[kst][rr] = *(const uint32_t*)(sm + row * AP + col * 2);
            qlf[kst][rr] = *(const uint32_t*)(sm + ASTG + row * AP + col * 2);
        }
    __syncthreads();

    const int trow = tid >> 2, tq = tid & 3;
    const __half* kh = g_kchi + (size_t)(cseg + trow) * HD + tq * 16;
    const __half* kl = g_kclo + (size_t)(cseg + trow) * HD + tq * 16;
    const size_t vbase = (size_t)hoff * HD + (size_t)trow * ntokc + csegrel + tq * 16;
    const __half* vh = g_vthi + vbase;
    const __half* vl = g_vtlo + vbase;
    const uint32_t ts = trow * AP + tq * 32;

    {
        char* st = sm;
        *(uint4*)(st + AKHI + ts)      = *(const uint4*)(kh);
        *(uint4*)(st + AKHI + ts + 16) = *(const uint4*)(kh + 8);
        *(uint4*)(st + AKLO + ts)      = *(const uint4*)(kl);
        *(uint4*)(st + AKLO + ts + 16) = *(const uint4*)(kl + 8);
        *(uint4*)(st + AVHI + ts)      = *(const uint4*)(vh);
        *(uint4*)(st + AVHI + ts + 16) = *(const uint4*)(vh + 8);
        *(uint4*)(st + AVLO + ts)      = *(const uint4*)(vl);
        *(uint4*)(st + AVLO + ts + 16) = *(const uint4*)(vl + 8);
    }
    __syncthreads();

    float oacc[8][4];
#pragma unroll
    for (int nd = 0; nd < 8; ++nd)
#pragma unroll
        for (int c = 0; c < 4; ++c) oacc[nd][c] = 0.f;
    float m0 = -CUDART_INF_F, m1 = -CUDART_INF_F, l0 = 0.f, l1 = 0.f;

    for (int kt = 0; kt < 32; ++kt) {
        const char* st = sm + (kt & 1) * ASTG;

        uint4 ra[8];
        if (kt < 31) {
            const int ko = (kt + 1) * 64;
            const size_t kof = (size_t)ko * HD;
            ra[0] = *(const uint4*)(kh + kof); ra[1] = *(const uint4*)(kh + kof + 8);
            ra[2] = *(const uint4*)(kl + kof); ra[3] = *(const uint4*)(kl + kof + 8);
            ra[4] = *(const uint4*)(vh + ko);  ra[5] = *(const uint4*)(vh + ko + 8);
            ra[6] = *(const uint4*)(vl + ko);  ra[7] = *(const uint4*)(vl + ko + 8);
        }

        float sacc[8][4];
#pragma unroll
        for (int t = 0; t < 8; ++t)
#pragma unroll
            for (int c = 0; c < 4; ++c) sacc[t][c] = 0.f;
#pragma unroll
        for (int kst = 0; kst < 4; ++kst)
#pragma unroll
            for (int ni = 0; ni < 8; ++ni) {
                const char* kb = st + AKHI + (ni * 8 + g) * AP + kst * 32 + q * 4;
                const char* lb = st + AKLO + (ni * 8 + g) * AP + kst * 32 + q * 4;
                uint32_t bh[2] = {*(const uint32_t*)kb, *(const uint32_t*)(kb + 16)};
                uint32_t bl[2] = {*(const uint32_t*)lb, *(const uint32_t*)(lb + 16)};
                mma16816(sacc[ni], qhf[kst], bh);
                mma16816(sacc[ni], qhf[kst], bl);
                mma16816(sacc[ni], qlf[kst], bh);
            }

        float rm0 = -CUDART_INF_F, rm1 = -CUDART_INF_F;
#pragma unroll
        for (int t = 0; t < 8; ++t) {
#pragma unroll
            for (int c = 0; c < 4; ++c) sacc[t][c] *= CSC;
            rm0 = fmaxf(rm0, fmaxf(sacc[t][0], sacc[t][1]));
            rm1 = fmaxf(rm1, fmaxf(sacc[t][2], sacc[t][3]));
        }
        rm0 = fmaxf(rm0, __shfl_xor_sync(0xffffffffu, rm0, 1));
        rm0 = fmaxf(rm0, __shfl_xor_sync(0xffffffffu, rm0, 2));
        rm1 = fmaxf(rm1, __shfl_xor_sync(0xffffffffu, rm1, 1));
        rm1 = fmaxf(rm1, __shfl_xor_sync(0xffffffffu, rm1, 2));
        const float mn0 = fmaxf(m0, rm0), mn1 = fmaxf(m1, rm1);
        const float cr0 = exp2_poly(m0 - mn0), cr1 = exp2_poly(m1 - mn1);
        m0 = mn0; m1 = mn1;

        float rs0 = 0.f, rs1 = 0.f;
#pragma unroll
        for (int t = 0; t < 8; ++t) {
            sacc[t][0] = exp2_poly(sacc[t][0] - mn0); rs0 += sacc[t][0];
            sacc[t][1] = exp2_poly(sacc[t][1] - mn0); rs0 += sacc[t][1];
            sacc[t][2] = exp2_poly(sacc[t][2] - mn1); rs1 += sacc[t][2];
            sacc[t][3] = exp2_poly(sacc[t][3] - mn1); rs1 += sacc[t][3];
        }
        rs0 += __shfl_xor_sync(0xffffffffu, rs0, 1);
        rs0 += __shfl_xor_sync(0xffffffffu, rs0, 2);
        rs1 += __shfl_xor_sync(0xffffffffu, rs1, 1);
        rs1 += __shfl_xor_sync(0xffffffffu, rs1, 2);
        l0 = l0 * cr0 + rs0;
        l1 = l1 * cr1 + rs1;
#pragma unroll
        for (int nd = 0; nd < 8; ++nd) {
            oacc[nd][0] *= cr0; oacc[nd][1] *= cr0;
            oacc[nd][2] *= cr1; oacc[nd][3] *= cr1;
        }

        // O += P V  (P packed to fp16 in registers; residual via cvt round trip)
#pragma unroll
        for (int kb = 0; kb < 4; ++kb) {
            uint32_t ah[4], al[4];
#pragma unroll
            for (int half = 0; half < 2; ++half) {
                const float* s0 = sacc[2 * kb + half];
                ah[2 * half]     = pack_f16x2(s0[1], s0[0]);
                ah[2 * half + 1] = pack_f16x2(s0[3], s0[2]);
                __half2 h0 = *(__half2*)&ah[2 * half];
                __half2 h1 = *(__half2*)&ah[2 * half + 1];
                const float e0 = s0[0] - __half2float(__low2half(h0));
                const float e1 = s0[1] - __half2float(__high2half(h0));
                const float e2 = s0[2] - __half2float(__low2half(h1));
                const float e3 = s0[3] - __half2float(__high2half(h1));
                al[2 * half]     = pack_f16x2(e1, e0);
                al[2 * half + 1] = pack_f16x2(e3, e2);
            }
#pragma unroll
            for (int nd = 0; nd < 8; ++nd) {
                const char* vb = st + AVHI + (nd * 8 + g) * AP + kb * 32 + q * 4;
                const char* wb = st + AVLO + (nd * 8 + g) * AP + kb * 32 + q * 4;
                uint32_t bh[2] = {*(const uint32_t*)vb, *(const uint32_t*)(vb + 16)};
                uint32_t bl[2] = {*(const uint32_t*)wb, *(const uint32_t*)(wb + 16)};
                mma16816(oacc[nd], ah, bh);
                mma16816(oacc[nd], al, bh);
                mma16816(oacc[nd], ah, bl);
            }
        }

        if (kt < 31) {
            char* dst = sm + ((kt + 1) & 1) * ASTG;
            *(uint4*)(dst + AKHI + ts)      = ra[0];
            *(uint4*)(dst + AKHI + ts + 16) = ra[1];
            *(uint4*)(dst + AKLO + ts)      = ra[2];
            *(uint4*)(dst + AKLO + ts + 16) = ra[3];
            *(uint4*)(dst + AVHI + ts)      = ra[4];
            *(uint4*)(dst + AVHI + ts + 16) = ra[5];
            *(uint4*)(dst + AVLO + ts)      = ra[6];
            *(uint4*)(dst + AVLO + ts + 16) = ra[7];
        }
        __syncthreads();
    }

    const float inv0 = 1.f / l0, inv1 = 1.f / l1;
    const int ci0 = csegrel + blockIdx.x * 128 + w * 16 + g;
    const int tok0 = off + ci0 * r;
    const int tok1 = off + (ci0 + 8) * r;
    float* o0 = g_o + (size_t)tok0 * EDIM + h * HD + q * 2;
    float* o1 = g_o + (size_t)tok1 * EDIM + h * HD + q * 2;
#pragma unroll
    for (int nd = 0; nd < 8; ++nd) {
        *(float2*)(o0 + nd * 8) = make_float2(oacc[nd][0] * inv0, oacc[nd][1] * inv0);
        *(float2*)(o1 + nd * 8) = make_float2(oacc[nd][2] * inv1, oacc[nd][3] * inv1);
    }
}

// ---------------------------------------------------------------------------
__global__ __launch_bounds__(256) void layernorm_k(
    const float* __restrict__ gamma, const float* __restrict__ beta)
{
    __shared__ float red[8];
    __shared__ float bcast;
    const int row = blockIdx.x;
    const int tid = threadIdx.x;
    const int lane = tid & 31, wid = tid >> 5;
    const float* x = g_o + (size_t)row * EDIM;
    float v0 = x[tid], v1 = x[tid + 256], v2 = x[tid + 512];

    float ssum = v0 + v1 + v2;
#pragma unroll
    for (int w = 16; w >= 1; w >>= 1) ssum += __shfl_xor_sync(0xffffffffu, ssum, w);
    if (lane == 0) red[wid] = ssum;
    __syncthreads();
    if (tid < 32) {
        float t = (tid < 8) ? red[tid] : 0.f;
#pragma unroll
        for (int w = 4; w >= 1; w >>= 1) t += __shfl_xor_sync(0xffffffffu, t, w);
        if (tid == 0) bcast = t;
    }
    __syncthreads();
    const float mu = bcast * (1.f / 768.f);
    float d0 = v0 - mu, d1 = v1 - mu, d2 = v2 - mu;
    float sq = d0 * d0 + d1 * d1 + d2 * d2;
#pragma unroll
    for (int w = 16; w >= 1; w >>= 1) sq += __shfl_xor_sync(0xffffffffu, sq, w);
    __syncthreads();
    if (lane == 0) red[wid] = sq;
    __syncthreads();
    if (tid < 32) {
        float t = (tid < 8) ? red[tid] : 0.f;
#pragma unroll
        for (int w = 4; w >= 1; w >>= 1) t += __shfl_xor_sync(0xffffffffu, t, w);
        if (tid == 0) bcast = t;
    }
    __syncthreads();
    const float rstd = rsqrtf(bcast * (1.f / 768.f) + 1e-5f);
    const size_t rb = (size_t)row * EDIM;
#pragma unroll
    for (int part = 0; part < 3; ++part) {
        const int idx = tid + part * 256;
        const float d = (part == 0) ? d0 : (part == 1) ? d1 : d2;
        const float y = d * rstd * gamma[idx] + beta[idx];
        __half h = __float2half_rn(y);
        g_onhi[rb + idx] = h;
        g_onlo[rb + idx] = __float2half_rn(y - __half2float(h));
    }
}

__global__ void zero_o() {
    ((float4*)g_o)[blockIdx.x * blockDim.x + threadIdx.x] =
        make_float4(0.f, 0.f, 0.f, 0.f);
}

// ---------------------------------------------------------------------------
extern "C" void kernel_launch(void* const* d_in, const int* in_sizes, int n_in,
                              void* d_out, int out_size)
{
    const float* x      = (const float*)d_in[0];
    const float* w_qkv  = (const float*)d_in[1];
    const float* b_qkv  = (const float*)d_in[2];
    const float* w_out  = (const float*)d_in[3];
    const float* b_out  = (const float*)d_in[4];
    const float* ln_g   = (const float*)d_in[5];
    const float* ln_b   = (const float*)d_in[6];
    float* out = (float*)d_out;

    const int SMEM_GEMM = 2 * STG_B;      // 80 KB
    const int SMEM_ATTN = 2 * ASTG;       // 72 KB
    cudaFuncSetAttribute(wgemm<0>, cudaFuncAttributeMaxDynamicSharedMemorySize, SMEM_GEMM);
    cudaFuncSetAttribute(wgemm<1>, cudaFuncAttributeMaxDynamicSharedMemorySize, SMEM_GEMM);
    cudaFuncSetAttribute(attn_tc, cudaFuncAttributeMaxDynamicSharedMemorySize, SMEM_ATTN);

    split_k<0><<<(NTOK * EDIM / 4) / 256, 256>>>(x);
    split_k<1><<<(E3 * EDIM / 4) / 256, 256>>>(w_qkv);
    split_k<2><<<(EDIM * EDIM / 4) / 256, 256>>>(w_out);

    dim3 g1(E3 / 128, NTOK / 128);
    wgemm<0><<<g1, 512, SMEM_GEMM>>>(b_qkv, nullptr);

    conv_qk<<<(NCROWS * 16) / 256, 256>>>();
    conv_v<<<NCROWS / 64, 256>>>();
    zero_o<<<(NTOK * EDIM / 4) / 256, 256>>>();

    dim3 g2(16, 28);
    attn_tc<<<g2, 256, SMEM_ATTN>>>();

    layernorm_k<<<NTOK, 256>>>(ln_g, ln_b);

    dim3 g3(EDIM / 128, NTOK / 128);
    wgemm<1><<<g3, 512, SMEM_GEMM>>>(b_out, out);
}

// round 17
// speedup vs baseline: 2.6440x; 1.3288x over previous
#include <cuda_runtime.h>
#include <cuda_fp16.h>
#include <math_constants.h>
#include <cstdint>

#define NTOK 8192
#define EDIM 768
#define E3   2304
#define HD   64
#define CSC  0.18033688011112042f   // 0.125 * log2(e)
#define NCROWS 57344                // 4*8192 + 4*4096 + 4*2048

__device__ float g_qkv[NTOK * E3];
__device__ float g_o[NTOK * EDIM];
__device__ __half g_xhi[NTOK * EDIM];
__device__ __half g_xlo[NTOK * EDIM];
__device__ __half g_wqhi[E3 * EDIM];     // weights: hi only (2-term split)
__device__ __half g_wohi[EDIM * EDIM];
__device__ __half g_onhi[NTOK * EDIM];
__device__ __half g_onlo[NTOK * EDIM];
__device__ __half g_qchi[NCROWS * HD];
__device__ __half g_qclo[NCROWS * HD];
__device__ __half g_kchi[NCROWS * HD];   // K: hi only
__device__ __half g_vthi[NCROWS * HD];   // Vt: hi only, [head][d][tokc]

__device__ __forceinline__ void mma16816(float* c, const uint32_t* a, const uint32_t* b)
{
    asm volatile(
        "mma.sync.aligned.m16n8k16.row.col.f32.f16.f16.f32 "
        "{%0,%1,%2,%3}, {%4,%5,%6,%7}, {%8,%9}, {%0,%1,%2,%3};"
        : "+f"(c[0]), "+f"(c[1]), "+f"(c[2]), "+f"(c[3])
        : "r"(a[0]), "r"(a[1]), "r"(a[2]), "r"(a[3]), "r"(b[0]), "r"(b[1]));
}

__device__ __forceinline__ void ldmx4(uint32_t& r0, uint32_t& r1, uint32_t& r2,
                                      uint32_t& r3, uint32_t addr)
{
    asm volatile("ldmatrix.sync.aligned.m8n8.x4.shared.b16 {%0,%1,%2,%3}, [%4];"
                 : "=r"(r0), "=r"(r1), "=r"(r2), "=r"(r3) : "r"(addr));
}

__device__ __forceinline__ uint32_t smem_u32(const void* p)
{
    uint32_t a;
    asm("{ .reg .u64 t; cvta.to.shared.u64 t, %1; cvt.u32.u64 %0, t; }"
        : "=r"(a) : "l"(p));
    return a;
}

__device__ __forceinline__ float exp2_poly(float t)
{
    t = fmaxf(t, -125.f);
    float ft = floorf(t);
    float f = t - ft;
    float p = 1.5403530e-4f;
    p = fmaf(p, f, 1.3333558e-3f);
    p = fmaf(p, f, 9.6181291e-3f);
    p = fmaf(p, f, 5.5504109e-2f);
    p = fmaf(p, f, 2.4022651e-1f);
    p = fmaf(p, f, 6.9314718e-1f);
    p = fmaf(p, f, 1.0f);
    return __int_as_float(__float_as_int(p) + (((int)ft) << 23));
}

__device__ __forceinline__ uint32_t pack_f16x2(float odd, float even)
{
    __half2 h = __floats2half2_rn(even, odd);
    return *(uint32_t*)&h;
}

__device__ __forceinline__ void decode_row(int row, int& h, int& tc, int& r, int& off)
{
    if (row < 32768)      { h = row >> 13;                tc = row & 8191; r = 1; off = 0; }
    else if (row < 49152) { int u = row - 32768; h = 4 + (u >> 12); tc = u & 4095; r = 2; off = 1; }
    else                  { int u = row - 49152; h = 8 + (u >> 11); tc = u & 2047; r = 4; off = 2; }
}

// ---------------------------------------------------------------------------
// wgemm: 2-term split-fp16 HMMA GEMM, C = (Ahi+Alo) @ Bhi^T + bias.
// 512 threads / 16 warps, warp tile 64x16, 128x128 CTA tile, 2-stage smem.
// Tiles per stage: Ahi, Alo, Bhi (3 x 10240 B).
// ---------------------------------------------------------------------------
#define TILE_B 10240
#define STG_B  30720

template <int MODE>
__global__ __launch_bounds__(512) void wgemm(const float* __restrict__ bias,
                                             float* __restrict__ Cout)
{
    constexpr int NTOT = (MODE == 0) ? E3 : EDIM;
    constexpr int NC = 24;
    extern __shared__ char smem[];

    const int tid = threadIdx.x;
    const int lane = tid & 31;
    const int wid = tid >> 5;
    const int rowBase = blockIdx.y << 7;
    const int colBase = blockIdx.x << 7;
    const int mBase = (wid & 1) * 64;
    const int nBase = (wid >> 1) * 16;

    const __half* Ahi = (MODE == 0) ? g_xhi : g_onhi;
    const __half* Alo = (MODE == 0) ? g_xlo : g_onlo;
    const __half* Bhi = (MODE == 0) ? g_wqhi : g_wohi;
    float* C = (MODE == 0) ? g_qkv : Cout;

    const int lr = tid >> 2;
    const int lq = tid & 3;
    const __half* gA0 = Ahi + (size_t)(rowBase + lr) * EDIM + lq * 8;
    const __half* gA1 = Alo + (size_t)(rowBase + lr) * EDIM + lq * 8;
    const __half* gB0 = Bhi + (size_t)(colBase + lr) * EDIM + lq * 8;
    const uint32_t soff = (uint32_t)(lr * 80 + lq * 16);

    const uint32_t smbase = smem_u32(smem);
    const int laneR = lane & 15;
    const int laneH = (lane >> 4) * 16;

    float acc[4][2][4];
#pragma unroll
    for (int mi = 0; mi < 4; ++mi)
#pragma unroll
        for (int ni = 0; ni < 2; ++ni)
#pragma unroll
            for (int r = 0; r < 4; ++r) acc[mi][ni][r] = 0.f;

    {
        char* st = smem;
        *(uint4*)(st + 0 * TILE_B + soff) = *(const uint4*)(gA0);
        *(uint4*)(st + 1 * TILE_B + soff) = *(const uint4*)(gA1);
        *(uint4*)(st + 2 * TILE_B + soff) = *(const uint4*)(gB0);
    }
    __syncthreads();

    const int g = lane >> 2;
    const int q = lane & 3;

    for (int c = 0; c < NC; ++c) {
        const int stg = c & 1;
        uint4 ra[3];
        if (c + 1 < NC) {
            const int off = (c + 1) * 32;
            ra[0] = *(const uint4*)(gA0 + off);
            ra[1] = *(const uint4*)(gA1 + off);
            ra[2] = *(const uint4*)(gB0 + off);
        }

        const uint32_t As = smbase + stg * STG_B;
#pragma unroll
        for (int k0 = 0; k0 < 32; k0 += 16) {
            uint32_t ahi[4][4], alo[4][4];
#pragma unroll
            for (int mi = 0; mi < 4; ++mi) {
                const uint32_t ad = As + (uint32_t)((mBase + mi * 16 + laneR) * 80
                                                    + k0 * 2 + laneH);
                ldmx4(ahi[mi][0], ahi[mi][1], ahi[mi][2], ahi[mi][3], ad);
                ldmx4(alo[mi][0], alo[mi][1], alo[mi][2], alo[mi][3], ad + TILE_B);
            }
            uint32_t bhi[2][2];
            {
                const uint32_t bd = As + 2 * TILE_B
                                  + (uint32_t)((nBase + laneR) * 80 + k0 * 2 + laneH);
                uint32_t r0, r1, r2, r3;
                ldmx4(r0, r1, r2, r3, bd);
                bhi[0][0] = r0; bhi[0][1] = r2;
                bhi[1][0] = r1; bhi[1][1] = r3;
            }
#pragma unroll
            for (int mi = 0; mi < 4; ++mi)
#pragma unroll
                for (int ni = 0; ni < 2; ++ni) {
                    mma16816(acc[mi][ni], ahi[mi], bhi[ni]);
                    mma16816(acc[mi][ni], alo[mi], bhi[ni]);
                }
        }

        if (c + 1 < NC) {
            char* st = smem + ((c + 1) & 1) * STG_B;
            *(uint4*)(st + 0 * TILE_B + soff) = ra[0];
            *(uint4*)(st + 1 * TILE_B + soff) = ra[1];
            *(uint4*)(st + 2 * TILE_B + soff) = ra[2];
        }
        __syncthreads();
    }

#pragma unroll
    for (int mi = 0; mi < 4; ++mi) {
        const int row0 = rowBase + mBase + mi * 16 + g;
#pragma unroll
        for (int ni = 0; ni < 2; ++ni) {
            const int colg = colBase + nBase + ni * 8 + q * 2;
            const float b0 = bias[colg], b1 = bias[colg + 1];
            float* c0 = C + (size_t)row0 * NTOT + colg;
            float* c1 = C + (size_t)(row0 + 8) * NTOT + colg;
            c0[0] = acc[mi][ni][0] + b0; c0[1] = acc[mi][ni][1] + b1;
            c1[0] = acc[mi][ni][2] + b0; c1[1] = acc[mi][ni][3] + b1;
        }
    }
}

// ---------------------------------------------------------------------------
// x -> split hi/lo (A operand)
__global__ void split_x(const float* __restrict__ src)
{
    const int i = blockIdx.x * blockDim.x + threadIdx.x;
    float4 v = ((const float4*)src)[i];
    float a[4] = {v.x, v.y, v.z, v.w};
    const int base = i * 4;
#pragma unroll
    for (int j = 0; j < 4; ++j) {
        __half h = __float2half_rn(a[j]);
        g_xhi[base + j] = h;
        g_xlo[base + j] = __float2half_rn(a[j] - __half2float(h));
    }
}

// weights -> hi only (B operand). WHICH 0: w_qkv, 1: w_out
template <int WHICH>
__global__ void cvt_w(const float* __restrict__ src)
{
    __half* hi = (WHICH == 0) ? g_wqhi : g_wohi;
    const int i = blockIdx.x * blockDim.x + threadIdx.x;
    float4 v = ((const float4*)src)[i];
    const int base = i * 4;
    hi[base + 0] = __float2half_rn(v.x);
    hi[base + 1] = __float2half_rn(v.y);
    hi[base + 2] = __float2half_rn(v.z);
    hi[base + 3] = __float2half_rn(v.w);
}

// qkv fp32 -> compact Q split, K hi-only
__global__ void conv_qk()
{
    const int idx = blockIdx.x * 256 + threadIdx.x;
    const int row = idx >> 4;
    const int j = (idx & 15) * 4;
    int h, tc, r, off;
    decode_row(row, h, tc, r, off);
    const int tok = off + tc * r;
    const float4 qv = *(const float4*)(g_qkv + (size_t)tok * E3 + h * HD + j);
    const float4 kv = *(const float4*)(g_qkv + (size_t)tok * E3 + EDIM + h * HD + j);
    float qa[4] = {qv.x, qv.y, qv.z, qv.w};
    float ka[4] = {kv.x, kv.y, kv.z, kv.w};
    __half qh[4], ql[4], kh[4];
#pragma unroll
    for (int t = 0; t < 4; ++t) {
        qh[t] = __float2half_rn(qa[t]);
        ql[t] = __float2half_rn(qa[t] - __half2float(qh[t]));
        kh[t] = __float2half_rn(ka[t]);
    }
    const size_t o = (size_t)row * HD + j;
    *(uint2*)(g_qchi + o) = *(uint2*)qh;
    *(uint2*)(g_qclo + o) = *(uint2*)ql;
    *(uint2*)(g_kchi + o) = *(uint2*)kh;
}

// qkv fp32 V -> compact transposed Vt hi-only [head][d][tokc]
__global__ __launch_bounds__(256) void conv_v()
{
    __shared__ float vs[64][65];
    const int tid = threadIdx.x;
    const int row64 = blockIdx.x * 64;
    int h, tc0, r, off;
    decode_row(row64, h, tc0, r, off);
    const int ntokc = (h < 4) ? 8192 : (h < 8) ? 4096 : 2048;
    const int hoff = (h < 4) ? h * 8192 : (h < 8) ? 32768 + (h - 4) * 4096
                                                  : 49152 + (h - 8) * 2048;
    {
        const int tr = tid >> 2;
        const int j = (tid & 3) * 16;
        const int tok = off + (tc0 + tr) * r;
        const float* vp = g_qkv + (size_t)tok * E3 + 2 * EDIM + h * HD + j;
#pragma unroll
        for (int i = 0; i < 4; ++i) {
            float4 v = *(const float4*)(vp + i * 4);
            vs[tr][j + i * 4 + 0] = v.x; vs[tr][j + i * 4 + 1] = v.y;
            vs[tr][j + i * 4 + 2] = v.z; vs[tr][j + i * 4 + 3] = v.w;
        }
    }
    __syncthreads();
    const int d = tid >> 2;
    const int k0 = (tid & 3) * 16;
    __half vh[16];
#pragma unroll
    for (int i = 0; i < 16; ++i)
        vh[i] = __float2half_rn(vs[k0 + i][d]);
    const size_t o = (size_t)hoff * HD + (size_t)d * ntokc + tc0 + k0;
    *(uint4*)(g_vthi + o)     = *(uint4*)vh;
    *(uint4*)(g_vthi + o + 8) = *(uint4*)(vh + 8);
}

// ---------------------------------------------------------------------------
// Tensor-core flash attention: Q split / K,V hi-only (2-term), P split in regs.
// smem/stage: {Khi, Vthi}[64][pitch 144B] = 18432 B; 2 stages = 36864 B.
// ---------------------------------------------------------------------------
#define AP 144
#define AKHI 0
#define AVHI 9216
#define ASTG 18432

__global__ __launch_bounds__(256) void attn_tc()
{
    extern __shared__ char sm[];
    const int tid = threadIdx.x;
    const int lane = tid & 31;
    const int w = tid >> 5;
    const int g = lane >> 2;
    const int q = lane & 3;

    const int p = blockIdx.y;
    int mseg, hh, grp;
    if (p < 16)      { grp = 0; mseg = p >> 2;        hh = p & 3; }
    else if (p < 24) { grp = 1; mseg = (p - 16) >> 2; hh = (p - 16) & 3; }
    else             { grp = 2; mseg = 0;             hh = p - 24; }
    const int h = grp * 4 + hh;
    const int r = 1 << grp;
    const int off = grp;
    const int ntokc = 8192 >> grp;
    const int hoff = (grp == 0) ? h * 8192 : (grp == 1) ? 32768 + hh * 4096
                                                        : 49152 + hh * 2048;
    const int csegrel = mseg * 2048;
    const int cseg = hoff + csegrel;

    // stage Q (hi->region0, lo->region1), read frags
    {
        const int row = tid >> 1, hf = tid & 1;
        const size_t go = (size_t)(cseg + blockIdx.x * 128 + row) * HD + hf * 32;
        uint4 a0 = *(const uint4*)(g_qchi + go);
        uint4 a1 = *(const uint4*)(g_qchi + go + 8);
        uint4 a2 = *(const uint4*)(g_qchi + go + 16);
        uint4 a3 = *(const uint4*)(g_qchi + go + 24);
        uint4 b0 = *(const uint4*)(g_qclo + go);
        uint4 b1 = *(const uint4*)(g_qclo + go + 8);
        uint4 b2 = *(const uint4*)(g_qclo + go + 16);
        uint4 b3 = *(const uint4*)(g_qclo + go + 24);
        char* d0 = sm + row * AP + hf * 64;
        char* d1 = sm + ASTG + row * AP + hf * 64;
        *(uint4*)d0        = a0; *(uint4*)(d0 + 16) = a1;
        *(uint4*)(d0 + 32) = a2; *(uint4*)(d0 + 48) = a3;
        *(uint4*)d1        = b0; *(uint4*)(d1 + 16) = b1;
        *(uint4*)(d1 + 32) = b2; *(uint4*)(d1 + 48) = b3;
    }
    __syncthreads();
    uint32_t qhf[4][4], qlf[4][4];
#pragma unroll
    for (int kst = 0; kst < 4; ++kst)
#pragma unroll
        for (int rr = 0; rr < 4; ++rr) {
            const int row = w * 16 + g + 8 * (rr & 1);
            const int col = kst * 16 + q * 2 + 8 * (rr >> 1);
            qhf[kst][rr] = *(const uint32_t*)(sm + row * AP + col * 2);
            qlf[kst][rr] = *(const uint32_t*)(sm + ASTG + row * AP + col * 2);
        }
    __syncthreads();

    const int trow = tid >> 2, tq = tid & 3;
    const __half* kh = g_kchi + (size_t)(cseg + trow) * HD + tq * 16;
    const size_t vbase = (size_t)hoff * HD + (size_t)trow * ntokc + csegrel + tq * 16;
    const __half* vh = g_vthi + vbase;
    const uint32_t ts = trow * AP + tq * 32;

    {   // preload tile 0 into stage 0
        char* st = sm;
        *(uint4*)(st + AKHI + ts)      = *(const uint4*)(kh);
        *(uint4*)(st + AKHI + ts + 16) = *(const uint4*)(kh + 8);
        *(uint4*)(st + AVHI + ts)      = *(const uint4*)(vh);
        *(uint4*)(st + AVHI + ts + 16) = *(const uint4*)(vh + 8);
    }
    __syncthreads();

    float oacc[8][4];
#pragma unroll
    for (int nd = 0; nd < 8; ++nd)
#pragma unroll
        for (int c = 0; c < 4; ++c) oacc[nd][c] = 0.f;
    float m0 = -CUDART_INF_F, m1 = -CUDART_INF_F, l0 = 0.f, l1 = 0.f;

    for (int kt = 0; kt < 32; ++kt) {
        const char* st = sm + (kt & 1) * ASTG;

        uint4 ra[4];
        if (kt < 31) {
            const int ko = (kt + 1) * 64;
            const size_t kof = (size_t)ko * HD;
            ra[0] = *(const uint4*)(kh + kof); ra[1] = *(const uint4*)(kh + kof + 8);
            ra[2] = *(const uint4*)(vh + ko);  ra[3] = *(const uint4*)(vh + ko + 8);
        }

        // S = (Qhi+Qlo) Khi^T
        float sacc[8][4];
#pragma unroll
        for (int t = 0; t < 8; ++t)
#pragma unroll
            for (int c = 0; c < 4; ++c) sacc[t][c] = 0.f;
#pragma unroll
        for (int kst = 0; kst < 4; ++kst)
#pragma unroll
            for (int ni = 0; ni < 8; ++ni) {
                const char* kb = st + AKHI + (ni * 8 + g) * AP + kst * 32 + q * 4;
                uint32_t bh[2] = {*(const uint32_t*)kb, *(const uint32_t*)(kb + 16)};
                mma16816(sacc[ni], qhf[kst], bh);
                mma16816(sacc[ni], qlf[kst], bh);
            }

        // online softmax, base-2
        float rm0 = -CUDART_INF_F, rm1 = -CUDART_INF_F;
#pragma unroll
        for (int t = 0; t < 8; ++t) {
#pragma unroll
            for (int c = 0; c < 4; ++c) sacc[t][c] *= CSC;
            rm0 = fmaxf(rm0, fmaxf(sacc[t][0], sacc[t][1]));
            rm1 = fmaxf(rm1, fmaxf(sacc[t][2], sacc[t][3]));
        }
        rm0 = fmaxf(rm0, __shfl_xor_sync(0xffffffffu, rm0, 1));
        rm0 = fmaxf(rm0, __shfl_xor_sync(0xffffffffu, rm0, 2));
        rm1 = fmaxf(rm1, __shfl_xor_sync(0xffffffffu, rm1, 1));
        rm1 = fmaxf(rm1, __shfl_xor_sync(0xffffffffu, rm1, 2));
        const float mn0 = fmaxf(m0, rm0), mn1 = fmaxf(m1, rm1);
        const float cr0 = exp2_poly(m0 - mn0), cr1 = exp2_poly(m1 - mn1);
        m0 = mn0; m1 = mn1;

        float rs0 = 0.f, rs1 = 0.f;
#pragma unroll
        for (int t = 0; t < 8; ++t) {
            sacc[t][0] = exp2_poly(sacc[t][0] - mn0); rs0 += sacc[t][0];
            sacc[t][1] = exp2_poly(sacc[t][1] - mn0); rs0 += sacc[t][1];
            sacc[t][2] = exp2_poly(sacc[t][2] - mn1); rs1 += sacc[t][2];
            sacc[t][3] = exp2_poly(sacc[t][3] - mn1); rs1 += sacc[t][3];
        }
        rs0 += __shfl_xor_sync(0xffffffffu, rs0, 1);
        rs0 += __shfl_xor_sync(0xffffffffu, rs0, 2);
        rs1 += __shfl_xor_sync(0xffffffffu, rs1, 1);
        rs1 += __shfl_xor_sync(0xffffffffu, rs1, 2);
        l0 = l0 * cr0 + rs0;
        l1 = l1 * cr1 + rs1;
#pragma unroll
        for (int nd = 0; nd < 8; ++nd) {
            oacc[nd][0] *= cr0; oacc[nd][1] *= cr0;
            oacc[nd][2] *= cr1; oacc[nd][3] *= cr1;
        }

        // O += (Phi+Plo) Vhi
#pragma unroll
        for (int kb = 0; kb < 4; ++kb) {
            uint32_t ah[4], al[4];
#pragma unroll
            for (int half = 0; half < 2; ++half) {
                const float* s0 = sacc[2 * kb + half];
                ah[2 * half]     = pack_f16x2(s0[1], s0[0]);
                ah[2 * half + 1] = pack_f16x2(s0[3], s0[2]);
                __half2 h0 = *(__half2*)&ah[2 * half];
                __half2 h1 = *(__half2*)&ah[2 * half + 1];
                const float e0 = s0[0] - __half2float(__low2half(h0));
                const float e1 = s0[1] - __half2float(__high2half(h0));
                const float e2 = s0[2] - __half2float(__low2half(h1));
                const float e3 = s0[3] - __half2float(__high2half(h1));
                al[2 * half]     = pack_f16x2(e1, e0);
                al[2 * half + 1] = pack_f16x2(e3, e2);
            }
#pragma unroll
            for (int nd = 0; nd < 8; ++nd) {
                const char* vb = st + AVHI + (nd * 8 + g) * AP + kb * 32 + q * 4;
                uint32_t bh[2] = {*(const uint32_t*)vb, *(const uint32_t*)(vb + 16)};
                mma16816(oacc[nd], ah, bh);
                mma16816(oacc[nd], al, bh);
            }
        }

        if (kt < 31) {
            char* dst = sm + ((kt + 1) & 1) * ASTG;
            *(uint4*)(dst + AKHI + ts)      = ra[0];
            *(uint4*)(dst + AKHI + ts + 16) = ra[1];
            *(uint4*)(dst + AVHI + ts)      = ra[2];
            *(uint4*)(dst + AVHI + ts + 16) = ra[3];
        }
        __syncthreads();
    }

    const float inv0 = 1.f / l0, inv1 = 1.f / l1;
    const int ci0 = csegrel + blockIdx.x * 128 + w * 16 + g;
    const int tok0 = off + ci0 * r;
    const int tok1 = off + (ci0 + 8) * r;
    float* o0 = g_o + (size_t)tok0 * EDIM + h * HD + q * 2;
    float* o1 = g_o + (size_t)tok1 * EDIM + h * HD + q * 2;
#pragma unroll
    for (int nd = 0; nd < 8; ++nd) {
        *(float2*)(o0 + nd * 8) = make_float2(oacc[nd][0] * inv0, oacc[nd][1] * inv0);
        *(float2*)(o1 + nd * 8) = make_float2(oacc[nd][2] * inv1, oacc[nd][3] * inv1);
    }
}

// ---------------------------------------------------------------------------
__global__ __launch_bounds__(256) void layernorm_k(
    const float* __restrict__ gamma, const float* __restrict__ beta)
{
    __shared__ float red[8];
    __shared__ float bcast;
    const int row = blockIdx.x;
    const int tid = threadIdx.x;
    const int lane = tid & 31, wid = tid >> 5;
    const float* x = g_o + (size_t)row * EDIM;
    float v0 = x[tid], v1 = x[tid + 256], v2 = x[tid + 512];

    float ssum = v0 + v1 + v2;
#pragma unroll
    for (int w = 16; w >= 1; w >>= 1) ssum += __shfl_xor_sync(0xffffffffu, ssum, w);
    if (lane == 0) red[wid] = ssum;
    __syncthreads();
    if (tid < 32) {
        float t = (tid < 8) ? red[tid] : 0.f;
#pragma unroll
        for (int w = 4; w >= 1; w >>= 1) t += __shfl_xor_sync(0xffffffffu, t, w);
        if (tid == 0) bcast = t;
    }
    __syncthreads();
    const float mu = bcast * (1.f / 768.f);
    float d0 = v0 - mu, d1 = v1 - mu, d2 = v2 - mu;
    float sq = d0 * d0 + d1 * d1 + d2 * d2;
#pragma unroll
    for (int w = 16; w >= 1; w >>= 1) sq += __shfl_xor_sync(0xffffffffu, sq, w);
    __syncthreads();
    if (lane == 0) red[wid] = sq;
    __syncthreads();
    if (tid < 32) {
        float t = (tid < 8) ? red[tid] : 0.f;
#pragma unroll
        for (int w = 4; w >= 1; w >>= 1) t += __shfl_xor_sync(0xffffffffu, t, w);
        if (tid == 0) bcast = t;
    }
    __syncthreads();
    const float rstd = rsqrtf(bcast * (1.f / 768.f) + 1e-5f);
    const size_t rb = (size_t)row * EDIM;
#pragma unroll
    for (int part = 0; part < 3; ++part) {
        const int idx = tid + part * 256;
        const float d = (part == 0) ? d0 : (part == 1) ? d1 : d2;
        const float y = d * rstd * gamma[idx] + beta[idx];
        __half h = __float2half_rn(y);
        g_onhi[rb + idx] = h;
        g_onlo[rb + idx] = __float2half_rn(y - __half2float(h));
    }
}

__global__ void zero_o() {
    ((float4*)g_o)[blockIdx.x * blockDim.x + threadIdx.x] =
        make_float4(0.f, 0.f, 0.f, 0.f);
}

// ---------------------------------------------------------------------------
extern "C" void kernel_launch(void* const* d_in, const int* in_sizes, int n_in,
                              void* d_out, int out_size)
{
    const float* x      = (const float*)d_in[0];
    const float* w_qkv  = (const float*)d_in[1];
    const float* b_qkv  = (const float*)d_in[2];
    const float* w_out  = (const float*)d_in[3];
    const float* b_out  = (const float*)d_in[4];
    const float* ln_g   = (const float*)d_in[5];
    const float* ln_b   = (const float*)d_in[6];
    float* out = (float*)d_out;

    const int SMEM_GEMM = 2 * STG_B;      // 60 KB
    const int SMEM_ATTN = 2 * ASTG;       // 36 KB
    cudaFuncSetAttribute(wgemm<0>, cudaFuncAttributeMaxDynamicSharedMemorySize, SMEM_GEMM);
    cudaFuncSetAttribute(wgemm<1>, cudaFuncAttributeMaxDynamicSharedMemorySize, SMEM_GEMM);
    cudaFuncSetAttribute(attn_tc, cudaFuncAttributeMaxDynamicSharedMemorySize, SMEM_ATTN);

    split_x<<<(NTOK * EDIM / 4) / 256, 256>>>(x);
    cvt_w<0><<<(E3 * EDIM / 4) / 256, 256>>>(w_qkv);
    cvt_w<1><<<(EDIM * EDIM / 4) / 256, 256>>>(w_out);

    dim3 g1(E3 / 128, NTOK / 128);
    wgemm<0><<<g1, 512, SMEM_GEMM>>>(b_qkv, nullptr);

    conv_qk<<<(NCROWS * 16) / 256, 256>>>();
    conv_v<<<NCROWS / 64, 256>>>();
    zero_o<<<(NTOK * EDIM / 4) / 256, 256>>>();

    dim3 g2(16, 28);
    attn_tc<<<g2, 256, SMEM_ATTN>>>();

    layernorm_k<<<NTOK, 256>>>(ln_g, ln_b);

    dim3 g3(EDIM / 128, NTOK / 128);
    wgemm<1><<<g3, 512, SMEM_GEMM>>>(b_out, out);
}